// round 15
// baseline (speedup 1.0000x reference)
#include <cuda_runtime.h>
#include <cuda_bf16.h>
#include <math.h>
#include <stdint.h>

#define BB 4
#define TT 4096
#define DD 1024
#define HEADS 16
#define HDIM 64
#define FF 4096
#define KK 512
#define BT (BB*TT)      // 16384
#define BKr (BB*KK)     // 2048

#define NW1 (DD*DD)
#define NWF (DD*FF)

// ---------------- scratch ----------------------------------------------------
__device__ float g_logits[BT];
__device__ float g_auxp[64];
__device__ int   g_idx[BKr];
__device__ float g_gates[BKr];
__device__ float g_xsel[BKr*DD];
__device__ float g_q[BKr*DD];      // qkv q; later split-K partial 0
__device__ float g_k[BKr*DD];      // qkv k; later split-K partial 1
__device__ float g_v[BKr*DD];
__device__ float g_x1[BKr*DD];
__device__ float g_gateb[BKr*FF];
__device__ float g_upb[BKr*FF];
__device__ __nv_bfloat16 g_hb[BKr*DD];
__device__ __nv_bfloat16 g_ob[BKr*DD];
__device__ __nv_bfloat16 g_h2b[BKr*DD];
__device__ __nv_bfloat16 g_mlpa[BKr*FF];
__device__ uint32_t g_wpack[(4*NW1 + 3*NWF)/2];

// ---------------- helpers ----------------------------------------------------
__device__ __forceinline__ float blk_sum(float v, float* red) {
    int lane = threadIdx.x & 31, w = threadIdx.x >> 5;
    #pragma unroll
    for (int o = 16; o; o >>= 1) v += __shfl_down_sync(0xffffffffu, v, o);
    if (lane == 0) red[w] = v;
    __syncthreads();
    int nw = (blockDim.x + 31) >> 5;
    if (threadIdx.x < 32) {
        float t = (threadIdx.x < nw) ? red[threadIdx.x] : 0.f;
        #pragma unroll
        for (int o = 16; o; o >>= 1) t += __shfl_down_sync(0xffffffffu, t, o);
        if (threadIdx.x == 0) red[0] = t;
    }
    __syncthreads();
    float r = red[0];
    __syncthreads();
    return r;
}

__device__ __forceinline__ uint32_t f2tf(float x) {
    uint32_t y;
    asm("cvt.rna.tf32.f32 %0, %1;" : "=r"(y) : "f"(x));
    return y;
}
__device__ __forceinline__ float rnd(float x) { return __uint_as_float(f2tf(x)); }

__device__ __forceinline__ uint32_t pack_bf2(float lo, float hi) {
    __nv_bfloat162 t = __floats2bfloat162_rn(lo, hi);
    return *(uint32_t*)&t;
}

__device__ __forceinline__ void cp16(void* s, const void* g) {
    uint32_t sa = (uint32_t)__cvta_generic_to_shared(s);
    asm volatile("cp.async.cg.shared.global [%0], [%1], 16;" :: "r"(sa), "l"(g));
}

#define MMA_BF16(d0,d1,d2,d3,a0,a1,a2,a3,b0,b1) \
    asm volatile("mma.sync.aligned.m16n8k16.row.col.f32.bf16.bf16.f32 " \
        "{%0,%1,%2,%3}, {%4,%5,%6,%7}, {%8,%9}, {%0,%1,%2,%3};" \
        : "+f"(d0), "+f"(d1), "+f"(d2), "+f"(d3) \
        : "r"(a0), "r"(a1), "r"(a2), "r"(a3), "r"(b0), "r"(b1))

#define MMA_TF32(d0,d1,d2,d3,a0,a1,a2,a3,b0,b1) \
    asm volatile("mma.sync.aligned.m16n8k8.row.col.f32.tf32.tf32.f32 " \
        "{%0,%1,%2,%3}, {%4,%5,%6,%7}, {%8,%9}, {%0,%1,%2,%3};" \
        : "+f"(d0), "+f"(d1), "+f"(d2), "+f"(d3) \
        : "r"(a0), "r"(a1), "r"(a2), "r"(a3), "r"(b0), "r"(b1))

// ---------------- fused weight pack ------------------------------------------
__global__ void pack_all(const float* __restrict__ wq, const float* __restrict__ wk,
                         const float* __restrict__ wv, const float* __restrict__ wo,
                         const float* __restrict__ wg, const float* __restrict__ wu,
                         const float* __restrict__ wd) {
    const int R1 = NW1/8;
    const int RF = NWF/8;
    int base = blockIdx.x * blockDim.x + threadIdx.x;
    int stride = gridDim.x * blockDim.x;
    #pragma unroll
    for (int it = 0; it < 4; it++) {
        int i = base + it * stride;
        const float* src; uint32_t* dst; int li, sh, nmask;
        if (i < 4*R1) {
            int r = i >> 17;
            li = i & (R1 - 1);
            src = (r==0) ? wq : (r==1) ? wk : (r==2) ? wv : wo;
            dst = g_wpack + (size_t)r * (NW1/2);
            sh = 10; nmask = DD - 1;
        } else {
            int j = i - 4*R1;
            int r = (j >= 2*RF) ? 2 : (j >= RF ? 1 : 0);
            li = j - r*RF;
            src = (r==0) ? wg : (r==1) ? wu : wd;
            dst = g_wpack + 4*(size_t)(NW1/2) + (size_t)r*(NWF/2);
            if (r == 2) { sh = 10; nmask = DD - 1; }
            else        { sh = 12; nmask = FF - 1; }
        }
        int flat = li * 4;
        int k2 = flat >> sh;
        int n0 = flat & nmask;
        int N = nmask + 1;
        float4 r0 = *(const float4*)&src[(size_t)(2*k2    )*N + n0];
        float4 r1 = *(const float4*)&src[(size_t)(2*k2 + 1)*N + n0];
        uint4 o;
        o.x = pack_bf2(r0.x, r1.x);
        o.y = pack_bf2(r0.y, r1.y);
        o.z = pack_bf2(r0.z, r1.z);
        o.w = pack_bf2(r0.w, r1.w);
        *(uint4*)&dst[(size_t)k2*N + n0] = o;
    }
}

// ---------------- router logits --------------------------------------------
__global__ void router_kernel(const float* __restrict__ hs, const float* __restrict__ wr) {
    int warp = (blockIdx.x * blockDim.x + threadIdx.x) >> 5;
    int lane = threadIdx.x & 31;
    if (warp >= BT) return;
    const float4* row = (const float4*)(hs + (size_t)warp * DD);
    const float4* w   = (const float4*)wr;
    float s = 0.f;
    #pragma unroll
    for (int it = 0; it < 8; it++) {
        float4 a = row[lane + 32 * it];
        float4 b = w[lane + 32 * it];
        s += a.x*b.x + a.y*b.y + a.z*b.z + a.w*b.w;
    }
    #pragma unroll
    for (int o = 16; o; o >>= 1) s += __shfl_down_sync(0xffffffffu, s, o);
    if (lane == 0) g_logits[warp] = s;
}

// ---------------- top-k: radix select + bitmap emit ---------------------------
__global__ void topk_kernel() {
    __shared__ uint32_t keys[TT];
    __shared__ int hist[256];
    __shared__ uint32_t gt_bm[128], eq_bm[128], sel_bm[128];
    __shared__ int epre[128], spre[128];
    __shared__ uint32_t s_prefix;
    __shared__ int s_need;
    int b = blockIdx.x, tid = threadIdx.x;

    for (int i = tid; i < TT; i += 1024) {
        uint32_t u = __float_as_uint(g_logits[b*TT + i]);
        keys[i] = (u & 0x80000000u) ? ~u : (u | 0x80000000u);
    }
    if (tid == 0) { s_prefix = 0u; s_need = KK; }
    if (tid < 128) { gt_bm[tid] = 0u; eq_bm[tid] = 0u; }
    __syncthreads();

    for (int shift = 24; shift >= 0; shift -= 8) {
        if (tid < 256) hist[tid] = 0;
        __syncthreads();
        uint32_t pfx = s_prefix;
        uint32_t pmask = (shift == 24) ? 0u : (0xFFFFFFFFu << (shift + 8));
        for (int i = tid; i < TT; i += 1024) {
            uint32_t k2 = keys[i];
            if ((k2 & pmask) == pfx)
                atomicAdd(&hist[(k2 >> shift) & 255], 1);
        }
        __syncthreads();
        if (tid < 32) {
            int need = s_need;
            int loc[8], lsum = 0;
            #pragma unroll
            for (int j = 0; j < 8; j++) { loc[j] = hist[tid*8 + j]; lsum += loc[j]; }
            int inc = lsum;
            #pragma unroll
            for (int o = 1; o < 32; o <<= 1) {
                int n = __shfl_up_sync(0xffffffffu, inc, o);
                if (tid >= o) inc += n;
            }
            int total = __shfl_sync(0xffffffffu, inc, 31);
            int run = inc - lsum;
            int bestb = -1, bestacc = 0;
            #pragma unroll
            for (int j = 0; j < 8; j++) {
                int cnt_lt = run; run += loc[j];
                if (loc[j] > 0 && total - cnt_lt >= need) {
                    bestb = tid*8 + j;
                    bestacc = total - cnt_lt - loc[j];
                }
            }
            #pragma unroll
            for (int o = 16; o; o >>= 1) {
                int ob = __shfl_down_sync(0xffffffffu, bestb, o);
                int oa = __shfl_down_sync(0xffffffffu, bestacc, o);
                if (ob > bestb) { bestb = ob; bestacc = oa; }
            }
            if (tid == 0) {
                s_need = need - bestacc;
                s_prefix = pfx | ((uint32_t)bestb << shift);
            }
        }
        __syncthreads();
    }

    uint32_t T = s_prefix;
    int need_eq = s_need;

    for (int i = tid; i < TT; i += 1024) {
        uint32_t k2 = keys[i];
        if (k2 > T)       atomicOr(&gt_bm[i >> 5], 1u << (i & 31));
        else if (k2 == T) atomicOr(&eq_bm[i >> 5], 1u << (i & 31));
    }
    __syncthreads();

    if (tid < 32) {
        int el[4], es = 0;
        #pragma unroll
        for (int j = 0; j < 4; j++) { el[j] = __popc(eq_bm[tid*4 + j]); es += el[j]; }
        int ei = es;
        #pragma unroll
        for (int o = 1; o < 32; o <<= 1) {
            int ne = __shfl_up_sync(0xffffffffu, ei, o);
            if (tid >= o) ei += ne;
        }
        int erun = ei - es;
        #pragma unroll
        for (int j = 0; j < 4; j++) { epre[tid*4 + j] = erun; erun += el[j]; }
    }
    __syncthreads();

    if (tid < 128) {
        uint32_t eqw = eq_bm[tid];
        int ep = epre[tid];
        uint32_t accm = 0u;
        if (ep < need_eq) {
            int take = need_eq - ep;
            int pc = __popc(eqw);
            if (take >= pc) accm = eqw;
            else {
                uint32_t m = eqw;
                for (int z = pc - take; z > 0; z--)
                    m &= ~(0x80000000u >> __clz(m));
                accm = m;
            }
        }
        sel_bm[tid] = gt_bm[tid] | accm;
    }
    __syncthreads();

    if (tid < 32) {
        int sl[4], ss = 0;
        #pragma unroll
        for (int j = 0; j < 4; j++) { sl[j] = __popc(sel_bm[tid*4 + j]); ss += sl[j]; }
        int si = ss;
        #pragma unroll
        for (int o = 1; o < 32; o <<= 1) {
            int n = __shfl_up_sync(0xffffffffu, si, o);
            if (tid >= o) si += n;
        }
        int srun = si - ss;
        #pragma unroll
        for (int j = 0; j < 4; j++) { spre[tid*4 + j] = srun; srun += sl[j]; }
    }
    __syncthreads();

    if (tid < 128) {
        uint32_t w = sel_bm[tid];
        int pos = spre[tid];
        while (w) {
            int bit = __ffs(w) - 1;
            w &= w - 1;
            int idx = tid*32 + bit;
            g_idx[b*KK + pos] = idx;
            float l = g_logits[b*TT + idx];
            g_gates[b*KK + pos] = 1.f / (1.f + expf(-l));
            pos++;
        }
    }
}

// ---------------- aux loss -----------------------------------------------------
__global__ void aux1_kernel() {
    __shared__ float red[32];
    float s = 0.f;
    for (int i = blockIdx.x * blockDim.x + threadIdx.x; i < BT; i += gridDim.x * blockDim.x) {
        float l = g_logits[i];
        s += fmaxf(l, 0.f) + log1pf(expf(-fabsf(l)));
    }
    float tot = blk_sum(s, red);
    if (threadIdx.x == 0) g_auxp[blockIdx.x] = tot;
}

__global__ void aux2_kernel(float* __restrict__ out, int aux_off) {
    __shared__ float red[32];
    float s = 0.f;
    if (threadIdx.x < 64) s = g_auxp[threadIdx.x];
    for (int i = threadIdx.x; i < BKr; i += blockDim.x) {
        int b = i >> 9;
        s -= g_logits[b*TT + g_idx[i]];
    }
    float tot = blk_sum(s, red);
    if (threadIdx.x == 0) out[aux_off] = tot * (0.01f / (float)BT);
}

// ---------------- gather + rmsnorm1 -> bf16 ---------------------------------
__global__ void gather_rms1(const float* __restrict__ hs, const float* __restrict__ ln1) {
    __shared__ float red[32];
    int bj = blockIdx.x;
    int b = bj >> 9;
    int row = g_idx[bj];
    const float4* src = (const float4*)(hs + ((size_t)(b*TT + row)) * DD);
    float4 x = src[threadIdx.x];
    float ss = x.x*x.x + x.y*x.y + x.z*x.z + x.w*x.w;
    float tot = blk_sum(ss, red);
    float r = rsqrtf(tot / (float)DD + 1e-6f);
    ((float4*)g_xsel)[bj*256 + threadIdx.x] = x;
    float4 w = ((const float4*)ln1)[threadIdx.x];
    uint32_t lo = pack_bf2(x.x*r*w.x, x.y*r*w.y);
    uint32_t hi = pack_bf2(x.z*r*w.z, x.w*r*w.w);
    *(uint2*)&g_hb[(size_t)bj*DD + threadIdx.x*4] = make_uint2(lo, hi);
}

// ---------------- combine wo split-K partials + rmsnorm2 -> bf16 -------------
__global__ void combine_rms2(const float* __restrict__ ln2) {
    __shared__ float red[32];
    int bj = blockIdx.x;
    int i = bj*256 + threadIdx.x;
    float4 xs = ((const float4*)g_xsel)[i];
    float4 p0 = ((const float4*)g_q)[i];
    float4 p1 = ((const float4*)g_k)[i];
    float4 x = make_float4(xs.x + p0.x + p1.x, xs.y + p0.y + p1.y,
                           xs.z + p0.z + p1.z, xs.w + p0.w + p1.w);
    ((float4*)g_x1)[i] = x;
    float ss = x.x*x.x + x.y*x.y + x.z*x.z + x.w*x.w;
    float tot = blk_sum(ss, red);
    float r = rsqrtf(tot / (float)DD + 1e-6f);
    float4 w = ((const float4*)ln2)[threadIdx.x];
    uint32_t lo = pack_bf2(x.x*r*w.x, x.y*r*w.y);
    uint32_t hi = pack_bf2(x.z*r*w.z, x.w*r*w.w);
    *(uint2*)&g_h2b[(size_t)bj*DD + threadIdx.x*4] = make_uint2(lo, hi);
}

// ---------------- BF16 tensor-core GEMM (2-stage cp.async, split-K) -----------
// out_mode: 0 = fp32, 1 = fp32 tf32-rounded, 5 = QKV (rope fused for z<2, rnd)
#define ASTR 20
#define BSTR 136
__global__ __launch_bounds__(256) void gemm_bf(
    const __nv_bfloat16* __restrict__ A,
    const uint32_t* __restrict__ B0, const uint32_t* __restrict__ B1, const uint32_t* __restrict__ B2,
    float* __restrict__ C0, float* __restrict__ C1, float* __restrict__ C2,
    int M, int N, int Ktot, int Klen, int koff_step, int out_mode)
{
    const uint32_t* B = (blockIdx.z == 0) ? B0 : (blockIdx.z == 1 ? B1 : B2);
    float*          C = (blockIdx.z == 0) ? C0 : (blockIdx.z == 1 ? C1 : C2);
    int kbase = (blockIdx.z * koff_step) >> 1;

    __shared__ uint32_t As[2][128][ASTR];
    __shared__ uint32_t Bs[2][16][BSTR];
    int tid = threadIdx.x;
    int w = tid >> 5, lane = tid & 31;
    int wm = w >> 1, wn = w & 1;
    int gid = lane >> 2, tid4 = lane & 3;
    int row0 = blockIdx.y * 128, col0 = blockIdx.x * 128;

    const uint32_t* Au = (const uint32_t*)A;
    int K2tot = Ktot >> 1;

    int arr = tid >> 1;
    int arc = (tid & 1) * 8;
    int brw = tid >> 4;
    int bcc = (tid & 15) * 4;

    float acc[2][8][4];
    #pragma unroll
    for (int i = 0; i < 2; i++)
        #pragma unroll
        for (int j = 0; j < 8; j++)
            #pragma unroll
            for (int c = 0; c < 4; c++) acc[i][j][c] = 0.f;

    int nt = Klen / 32;

    cp16(&As[0][arr][arc],     &Au[(size_t)(row0 + arr)*K2tot + kbase + arc]);
    cp16(&As[0][arr][arc + 4], &Au[(size_t)(row0 + arr)*K2tot + kbase + arc + 4]);
    cp16(&Bs[0][brw][bcc],      &B[(size_t)(kbase + brw)*N + col0 + bcc]);
    cp16(&Bs[0][brw][bcc + 64], &B[(size_t)(kbase + brw)*N + col0 + bcc + 64]);
    asm volatile("cp.async.commit_group;");

    int buf = 0;
    for (int t = 0; t < nt; t++) {
        if (t + 1 < nt) {
            int k2o = kbase + (t + 1) * 16;
            cp16(&As[buf^1][arr][arc],     &Au[(size_t)(row0 + arr)*K2tot + k2o + arc]);
            cp16(&As[buf^1][arr][arc + 4], &Au[(size_t)(row0 + arr)*K2tot + k2o + arc + 4]);
            cp16(&Bs[buf^1][brw][bcc],      &B[(size_t)(k2o + brw)*N + col0 + bcc]);
            cp16(&Bs[buf^1][brw][bcc + 64], &B[(size_t)(k2o + brw)*N + col0 + bcc + 64]);
            asm volatile("cp.async.commit_group;");
            asm volatile("cp.async.wait_group 1;");
        } else {
            asm volatile("cp.async.wait_group 0;");
        }
        __syncthreads();

        #pragma unroll
        for (int ks = 0; ks < 2; ks++) {
            int kb = ks * 8;
            uint32_t af[2][4];
            #pragma unroll
            for (int mt = 0; mt < 2; mt++) {
                int rm = wm*32 + mt*16;
                af[mt][0] = As[buf][rm + gid    ][kb + tid4    ];
                af[mt][1] = As[buf][rm + gid + 8][kb + tid4    ];
                af[mt][2] = As[buf][rm + gid    ][kb + tid4 + 4];
                af[mt][3] = As[buf][rm + gid + 8][kb + tid4 + 4];
            }
            #pragma unroll
            for (int n2 = 0; n2 < 8; n2++) {
                int cn = wn*64 + n2*8 + gid;
                uint32_t b0 = Bs[buf][kb + tid4    ][cn];
                uint32_t b1 = Bs[buf][kb + tid4 + 4][cn];
                MMA_BF16(acc[0][n2][0], acc[0][n2][1], acc[0][n2][2], acc[0][n2][3],
                         af[0][0], af[0][1], af[0][2], af[0][3], b0, b1);
                MMA_BF16(acc[1][n2][0], acc[1][n2][1], acc[1][n2][2], acc[1][n2][3],
                         af[1][0], af[1][1], af[1][2], af[1][3], b0, b1);
            }
        }
        __syncthreads();
        buf ^= 1;
    }

    if (out_mode == 5) {
        bool dorope = (blockIdx.z < 2);
        #pragma unroll
        for (int mt = 0; mt < 2; mt++) {
            int row = row0 + wm*32 + mt*16 + gid;
            float posA = 0.f, posB = 0.f;
            if (dorope) {
                posA = (float)g_idx[row];
                posB = (float)g_idx[row + 8];
            }
            #pragma unroll
            for (int n2 = 0; n2 < 4; n2++) {
                int col = col0 + wn*64 + n2*8 + tid4*2;
                float x1a = acc[mt][n2][0],   x1b = acc[mt][n2][1];
                float x1c = acc[mt][n2][2],   x1d = acc[mt][n2][3];
                float x2a = acc[mt][n2+4][0], x2b = acc[mt][n2+4][1];
                float x2c = acc[mt][n2+4][2], x2d = acc[mt][n2+4][3];
                float o1a, o1b, o1c, o1d, o2a, o2b, o2c, o2d;
                if (dorope) {
                    int d0 = col & 63;
                    float inv0 = expf(-logf(10000.f) * (float)d0 / 32.f);
                    float inv1 = expf(-logf(10000.f) * (float)(d0 + 1) / 32.f);
                    float cA0, sA0, cA1, sA1, cB0, sB0, cB1, sB1;
                    __sincosf(posA * inv0, &sA0, &cA0);
                    __sincosf(posA * inv1, &sA1, &cA1);
                    __sincosf(posB * inv0, &sB0, &cB0);
                    __sincosf(posB * inv1, &sB1, &cB1);
                    o1a = x1a*cA0 - x2a*sA0;  o2a = x2a*cA0 + x1a*sA0;
                    o1b = x1b*cA1 - x2b*sA1;  o2b = x2b*cA1 + x1b*sA1;
                    o1c = x1c*cB0 - x2c*sB0;  o2c = x2c*cB0 + x1c*sB0;
                    o1d = x1d*cB1 - x2d*sB1;  o2d = x2d*cB1 + x1d*sB1;
                } else {
                    o1a = x1a; o1b = x1b; o1c = x1c; o1d = x1d;
                    o2a = x2a; o2b = x2b; o2c = x2c; o2d = x2d;
                }
                *(float2*)&C[(size_t)row*N + col]          = make_float2(rnd(o1a), rnd(o1b));
                *(float2*)&C[(size_t)(row+8)*N + col]      = make_float2(rnd(o1c), rnd(o1d));
                *(float2*)&C[(size_t)row*N + col + 32]     = make_float2(rnd(o2a), rnd(o2b));
                *(float2*)&C[(size_t)(row+8)*N + col + 32] = make_float2(rnd(o2c), rnd(o2d));
            }
        }
    } else {
        #pragma unroll
        for (int mt = 0; mt < 2; mt++) {
            int row = row0 + wm*32 + mt*16 + gid;
            #pragma unroll
            for (int n2 = 0; n2 < 8; n2++) {
                int col = col0 + wn*64 + n2*8 + tid4*2;
                float2 v0 = make_float2(acc[mt][n2][0], acc[mt][n2][1]);
                float2 v1 = make_float2(acc[mt][n2][2], acc[mt][n2][3]);
                if (out_mode == 1) {
                    v0.x = rnd(v0.x); v0.y = rnd(v0.y);
                    v1.x = rnd(v1.x); v1.y = rnd(v1.y);
                }
                *(float2*)&C[(size_t)row*N + col]     = v0;
                *(float2*)&C[(size_t)(row+8)*N + col] = v1;
            }
        }
    }
}

// ---------------- tf32 flash attention, bf16 output, heavy-first --------------
__global__ __launch_bounds__(128) void attn_tc() {
    __shared__ float Qs[64][68];
    __shared__ float Ks[64][68];
    __shared__ float Vs[64][72];
    __shared__ float Ps[4][16][68];
    int qt = gridDim.x - 1 - blockIdx.x;
    int h = blockIdx.y, b = blockIdx.z;
    int tid = threadIdx.x, w = tid >> 5, lane = tid & 31;
    int gid = lane >> 2, tid4 = lane & 3;

    for (int f = tid; f < 64*16; f += 128) {
        int q = f >> 4, d4 = (f & 15) << 2;
        *(float4*)&Qs[q][d4] =
            *(const float4*)&g_q[((size_t)((b*KK + qt*64 + q)*HEADS + h))*HDIM + d4];
    }

    int r0g = qt*64 + w*16 + gid;
    int r1g = r0g + 8;

    float m0 = -1e30f, m1 = -1e30f, l0 = 0.f, l1 = 0.f;
    float oa[8][4];
    #pragma unroll
    for (int n2 = 0; n2 < 8; n2++)
        #pragma unroll
        for (int c = 0; c < 4; c++) oa[n2][c] = 0.f;

    for (int kt = 0; kt <= qt; kt++) {
        __syncthreads();
        for (int f = tid; f < 64*16; f += 128) {
            int k = f >> 4, d4 = (f & 15) << 2;
            size_t base = ((size_t)((b*KK + kt*64 + k)*HEADS + h))*HDIM + d4;
            *(float4*)&Ks[k][d4] = *(const float4*)&g_k[base];
            *(float4*)&Vs[k][d4] = *(const float4*)&g_v[base];
        }
        __syncthreads();

        float sc[8][4];
        #pragma unroll
        for (int n2 = 0; n2 < 8; n2++)
            #pragma unroll
            for (int c = 0; c < 4; c++) sc[n2][c] = 0.f;

        #pragma unroll
        for (int ks = 0; ks < 8; ks++) {
            int kb = ks * 8;
            uint32_t a0 = __float_as_uint(Qs[w*16 + gid    ][kb + tid4    ]);
            uint32_t a1 = __float_as_uint(Qs[w*16 + gid + 8][kb + tid4    ]);
            uint32_t a2 = __float_as_uint(Qs[w*16 + gid    ][kb + tid4 + 4]);
            uint32_t a3 = __float_as_uint(Qs[w*16 + gid + 8][kb + tid4 + 4]);
            #pragma unroll
            for (int n2 = 0; n2 < 8; n2++) {
                uint32_t b0 = __float_as_uint(Ks[n2*8 + gid][kb + tid4    ]);
                uint32_t b1 = __float_as_uint(Ks[n2*8 + gid][kb + tid4 + 4]);
                MMA_TF32(sc[n2][0], sc[n2][1], sc[n2][2], sc[n2][3],
                         a0, a1, a2, a3, b0, b1);
            }
        }

        bool diag = (kt == qt);
        float mx0 = -1e30f, mx1 = -1e30f;
        #pragma unroll
        for (int n2 = 0; n2 < 8; n2++) {
            int col = kt*64 + n2*8 + 2*tid4;
            sc[n2][0] *= 0.125f; sc[n2][1] *= 0.125f;
            sc[n2][2] *= 0.125f; sc[n2][3] *= 0.125f;
            if (diag) {
                if (col     > r0g) sc[n2][0] = -1e30f;
                if (col + 1 > r0g) sc[n2][1] = -1e30f;
                if (col     > r1g) sc[n2][2] = -1e30f;
                if (col + 1 > r1g) sc[n2][3] = -1e30f;
            }
            mx0 = fmaxf(mx0, fmaxf(sc[n2][0], sc[n2][1]));
            mx1 = fmaxf(mx1, fmaxf(sc[n2][2], sc[n2][3]));
        }
        #pragma unroll
        for (int o = 1; o <= 2; o <<= 1) {
            mx0 = fmaxf(mx0, __shfl_xor_sync(0xffffffffu, mx0, o));
            mx1 = fmaxf(mx1, __shfl_xor_sync(0xffffffffu, mx1, o));
        }
        float mn0 = fmaxf(m0, mx0), mn1 = fmaxf(m1, mx1);
        float cor0 = __expf(m0 - mn0), cor1 = __expf(m1 - mn1);
        m0 = mn0; m1 = mn1;
        float rs0 = 0.f, rs1 = 0.f;
        #pragma unroll
        for (int n2 = 0; n2 < 8; n2++) {
            float p0 = __expf(sc[n2][0] - mn0);
            float p1 = __expf(sc[n2][1] - mn0);
            float p2 = __expf(sc[n2][2] - mn1);
            float p3 = __expf(sc[n2][3] - mn1);
            rs0 += p0 + p1; rs1 += p2 + p3;
            *(float2*)&Ps[w][gid    ][n2*8 + 2*tid4] = make_float2(rnd(p0), rnd(p1));
            *(float2*)&Ps[w][gid + 8][n2*8 + 2*tid4] = make_float2(rnd(p2), rnd(p3));
        }
        #pragma unroll
        for (int o = 1; o <= 2; o <<= 1) {
            rs0 += __shfl_xor_sync(0xffffffffu, rs0, o);
            rs1 += __shfl_xor_sync(0xffffffffu, rs1, o);
        }
        l0 = l0 * cor0 + rs0;
        l1 = l1 * cor1 + rs1;
        #pragma unroll
        for (int n2 = 0; n2 < 8; n2++) {
            oa[n2][0] *= cor0; oa[n2][1] *= cor0;
            oa[n2][2] *= cor1; oa[n2][3] *= cor1;
        }
        __syncwarp();

        #pragma unroll
        for (int ks = 0; ks < 8; ks++) {
            uint32_t a0 = __float_as_uint(Ps[w][gid    ][ks*8 + tid4    ]);
            uint32_t a1 = __float_as_uint(Ps[w][gid + 8][ks*8 + tid4    ]);
            uint32_t a2 = __float_as_uint(Ps[w][gid    ][ks*8 + tid4 + 4]);
            uint32_t a3 = __float_as_uint(Ps[w][gid + 8][ks*8 + tid4 + 4]);
            #pragma unroll
            for (int n2 = 0; n2 < 8; n2++) {
                uint32_t b0 = __float_as_uint(Vs[ks*8 + tid4    ][n2*8 + gid]);
                uint32_t b1 = __float_as_uint(Vs[ks*8 + tid4 + 4][n2*8 + gid]);
                MMA_TF32(oa[n2][0], oa[n2][1], oa[n2][2], oa[n2][3],
                         a0, a1, a2, a3, b0, b1);
            }
        }
        __syncwarp();
    }

    float i0 = 1.f / l0, i1 = 1.f / l1;
    #pragma unroll
    for (int n2 = 0; n2 < 8; n2++) {
        int d = n2*8 + 2*tid4;
        uint32_t p0 = pack_bf2(oa[n2][0]*i0, oa[n2][1]*i0);
        uint32_t p1 = pack_bf2(oa[n2][2]*i1, oa[n2][3]*i1);
        *(uint32_t*)&g_ob[((size_t)((b*KK + r0g)*HEADS + h))*HDIM + d] = p0;
        *(uint32_t*)&g_ob[((size_t)((b*KK + r1g)*HEADS + h))*HDIM + d] = p1;
    }
}

// ---------------- silu(gate)*up -> bf16 --------------------------------------
__global__ void silu_mul_kernel() {
    int i = blockIdx.x * blockDim.x + threadIdx.x;
    const int N4 = BKr*FF/4;
    if (i >= N4) return;
    float4 g = ((const float4*)g_gateb)[i];
    float4 u = ((const float4*)g_upb)[i];
    float a = g.x / (1.f + __expf(-g.x)) * u.x;
    float b = g.y / (1.f + __expf(-g.y)) * u.y;
    float c = g.z / (1.f + __expf(-g.z)) * u.z;
    float d = g.w / (1.f + __expf(-g.w)) * u.w;
    *(uint2*)&g_mlpa[(size_t)i*4] = make_uint2(pack_bf2(a, b), pack_bf2(c, d));
}

// ---------------- scatter: combine down split-K + gated residual --------------
__global__ void scatter_kernel(float* __restrict__ out) {
    int bj = blockIdx.x;
    int b = bj >> 9;
    int row = g_idx[bj];
    float gate = g_gates[bj];
    int i = bj*256 + threadIdx.x;
    float4 xs = ((const float4*)g_xsel)[i];
    float4 x1 = ((const float4*)g_x1)[i];
    float4 p0 = ((const float4*)g_q)[i];
    float4 p1 = ((const float4*)g_k)[i];
    float4 o;
    o.x = xs.x + gate*((x1.x + p0.x + p1.x) - xs.x);
    o.y = xs.y + gate*((x1.y + p0.y + p1.y) - xs.y);
    o.z = xs.z + gate*((x1.z + p0.z + p1.z) - xs.z);
    o.w = xs.w + gate*((x1.w + p0.w + p1.w) - xs.w);
    ((float4*)out)[((size_t)(b*TT + row))*256 + threadIdx.x] = o;
}

// ---------------- launch -------------------------------------------------------
extern "C" void kernel_launch(void* const* d_in, const int* in_sizes, int n_in,
                              void* d_out, int out_size) {
    const float* hs  = (const float*)d_in[0];
    const float* wr  = (const float*)d_in[1];
    const float* wq  = (const float*)d_in[2];
    const float* wk  = (const float*)d_in[3];
    const float* wv  = (const float*)d_in[4];
    const float* wo  = (const float*)d_in[5];
    const float* ln1 = (const float*)d_in[6];
    const float* ln2 = (const float*)d_in[7];
    const float* wg  = (const float*)d_in[8];
    const float* wu  = (const float*)d_in[9];
    const float* wd  = (const float*)d_in[10];
    float* out = (float*)d_out;

    static cudaStream_t s2 = nullptr;
    static cudaEvent_t evA = nullptr, evB = nullptr, evC = nullptr;
    if (!s2) {
        cudaStreamCreateWithFlags(&s2, cudaStreamNonBlocking);
        cudaEventCreateWithFlags(&evA, cudaEventDisableTiming);
        cudaEventCreateWithFlags(&evB, cudaEventDisableTiming);
        cudaEventCreateWithFlags(&evC, cudaEventDisableTiming);
    }

    float *p_q, *p_k, *p_v, *p_gate, *p_up;
    __nv_bfloat16 *p_hb, *p_ob, *p_h2b, *p_mlpa;
    uint32_t *p_wp;
    cudaGetSymbolAddress((void**)&p_q,    g_q);
    cudaGetSymbolAddress((void**)&p_k,    g_k);
    cudaGetSymbolAddress((void**)&p_v,    g_v);
    cudaGetSymbolAddress((void**)&p_gate, g_gateb);
    cudaGetSymbolAddress((void**)&p_up,   g_upb);
    cudaGetSymbolAddress((void**)&p_hb,   g_hb);
    cudaGetSymbolAddress((void**)&p_ob,   g_ob);
    cudaGetSymbolAddress((void**)&p_h2b,  g_h2b);
    cudaGetSymbolAddress((void**)&p_mlpa, g_mlpa);
    cudaGetSymbolAddress((void**)&p_wp,   g_wpack);

    uint32_t* rwq = p_wp;
    uint32_t* rwk = p_wp + NW1/2;
    uint32_t* rwv = p_wp + 2*(NW1/2);
    uint32_t* rwo = p_wp + 3*(NW1/2);
    uint32_t* rwg = p_wp + 4*(NW1/2);
    uint32_t* rwu = p_wp + 4*(NW1/2) + NWF/2;
    uint32_t* rwd = p_wp + 4*(NW1/2) + 2*(NWF/2);

    // fork: side stream packs weights FIRST (QKV needs it), then copies
    // hidden->out (only scatter needs it, joined at the very end).
    cudaEventRecord(evA, 0);
    cudaStreamWaitEvent(s2, evA, 0);
    pack_all<<<2048, 256, 0, s2>>>(wq, wk, wv, wo, wg, wu, wd);
    cudaEventRecord(evB, s2);
    cudaMemcpyAsync(out, hs, (size_t)BT*DD*sizeof(float), cudaMemcpyDeviceToDevice, s2);
    cudaEventRecord(evC, s2);

    // main front chain: router -> topk -> gather (aux1 off the critical path)
    router_kernel<<<BT/8, 256>>>(hs, wr);
    topk_kernel<<<BB, 1024>>>();
    gather_rms1<<<BKr, 256>>>(hs, ln1);
    aux1_kernel<<<64, 256>>>();

    cudaStreamWaitEvent(0, evB, 0);

    // fused QKV with in-epilogue RoPE (q,k) + tf32 rounding
    gemm_bf<<<dim3(DD/128, BKr/128, 3), 256>>>(p_hb, rwq, rwk, rwv,
                                               p_q, p_k, p_v,
                                               BKr, DD, DD, DD, 0, 5);

    // aux2 off the critical path: overlaps with QKV tail
    aux2_kernel<<<1, 1024>>>(out, out_size - 1);

    attn_tc<<<dim3(KK/64, HEADS, BB), 128>>>();

    // wo: split-K x2 into g_q/g_k partials
    gemm_bf<<<dim3(DD/128, BKr/128, 2), 256>>>(p_ob, rwo, rwo, rwo,
                                               p_q, p_k, p_k,
                                               BKr, DD, DD, DD/2, DD/2, 0);
    combine_rms2<<<BKr, 256>>>(ln2);

    // gate/up fused
    gemm_bf<<<dim3(FF/128, BKr/128, 2), 256>>>(p_h2b, rwg, rwu, rwu,
                                               p_gate, p_up, p_up,
                                               BKr, FF, DD, DD, 0, 0);
    silu_mul_kernel<<<(BKr*FF/4 + 255)/256, 256>>>();

    // down: split-K x2 into g_q/g_k partials
    gemm_bf<<<dim3(DD/128, BKr/128, 2), 256>>>(p_mlpa, rwd, rwd, rwd,
                                               p_q, p_k, p_k,
                                               BKr, DD, FF, FF/2, FF/2, 0);

    // join the out-copy right before the scatter that overwrites selected rows
    cudaStreamWaitEvent(0, evC, 0);
    scatter_kernel<<<BKr, 256>>>(out);
}

// round 16
// speedup vs baseline: 1.0009x; 1.0009x over previous
#include <cuda_runtime.h>
#include <cuda_bf16.h>
#include <math.h>
#include <stdint.h>

#define BB 4
#define TT 4096
#define DD 1024
#define HEADS 16
#define HDIM 64
#define FF 4096
#define KK 512
#define BT (BB*TT)      // 16384
#define BKr (BB*KK)     // 2048

#define NW1 (DD*DD)
#define NWF (DD*FF)

// ---------------- scratch ----------------------------------------------------
__device__ float g_logits[BT];
__device__ float g_auxp[64];
__device__ int   g_idx[BKr];
__device__ float g_gates[BKr];
__device__ float g_xsel[BKr*DD];
__device__ float g_q[BKr*DD];      // qkv q; later split-K partial 0
__device__ float g_k[BKr*DD];      // qkv k; later split-K partial 1
__device__ float g_v[BKr*DD];
__device__ float g_x1[BKr*DD];
__device__ float g_gateb[BKr*FF];
__device__ float g_upb[BKr*FF];
__device__ __nv_bfloat16 g_hb[BKr*DD];
__device__ __nv_bfloat16 g_ob[BKr*DD];
__device__ __nv_bfloat16 g_h2b[BKr*DD];
__device__ __nv_bfloat16 g_mlpa[BKr*FF];
__device__ uint32_t g_wpack[(4*NW1 + 3*NWF)/2];

// ---------------- helpers ----------------------------------------------------
__device__ __forceinline__ float blk_sum(float v, float* red) {
    int lane = threadIdx.x & 31, w = threadIdx.x >> 5;
    #pragma unroll
    for (int o = 16; o; o >>= 1) v += __shfl_down_sync(0xffffffffu, v, o);
    if (lane == 0) red[w] = v;
    __syncthreads();
    int nw = (blockDim.x + 31) >> 5;
    if (threadIdx.x < 32) {
        float t = (threadIdx.x < nw) ? red[threadIdx.x] : 0.f;
        #pragma unroll
        for (int o = 16; o; o >>= 1) t += __shfl_down_sync(0xffffffffu, t, o);
        if (threadIdx.x == 0) red[0] = t;
    }
    __syncthreads();
    float r = red[0];
    __syncthreads();
    return r;
}

__device__ __forceinline__ uint32_t f2tf(float x) {
    uint32_t y;
    asm("cvt.rna.tf32.f32 %0, %1;" : "=r"(y) : "f"(x));
    return y;
}
__device__ __forceinline__ float rnd(float x) { return __uint_as_float(f2tf(x)); }

__device__ __forceinline__ uint32_t pack_bf2(float lo, float hi) {
    __nv_bfloat162 t = __floats2bfloat162_rn(lo, hi);
    return *(uint32_t*)&t;
}

__device__ __forceinline__ void cp16(void* s, const void* g) {
    uint32_t sa = (uint32_t)__cvta_generic_to_shared(s);
    asm volatile("cp.async.cg.shared.global [%0], [%1], 16;" :: "r"(sa), "l"(g));
}

#define MMA_BF16(d0,d1,d2,d3,a0,a1,a2,a3,b0,b1) \
    asm volatile("mma.sync.aligned.m16n8k16.row.col.f32.bf16.bf16.f32 " \
        "{%0,%1,%2,%3}, {%4,%5,%6,%7}, {%8,%9}, {%0,%1,%2,%3};" \
        : "+f"(d0), "+f"(d1), "+f"(d2), "+f"(d3) \
        : "r"(a0), "r"(a1), "r"(a2), "r"(a3), "r"(b0), "r"(b1))

#define MMA_TF32(d0,d1,d2,d3,a0,a1,a2,a3,b0,b1) \
    asm volatile("mma.sync.aligned.m16n8k8.row.col.f32.tf32.tf32.f32 " \
        "{%0,%1,%2,%3}, {%4,%5,%6,%7}, {%8,%9}, {%0,%1,%2,%3};" \
        : "+f"(d0), "+f"(d1), "+f"(d2), "+f"(d3) \
        : "r"(a0), "r"(a1), "r"(a2), "r"(a3), "r"(b0), "r"(b1))

// ---------------- fused weight pack ------------------------------------------
__global__ void pack_all(const float* __restrict__ wq, const float* __restrict__ wk,
                         const float* __restrict__ wv, const float* __restrict__ wo,
                         const float* __restrict__ wg, const float* __restrict__ wu,
                         const float* __restrict__ wd) {
    const int R1 = NW1/8;
    const int RF = NWF/8;
    int base = blockIdx.x * blockDim.x + threadIdx.x;
    int stride = gridDim.x * blockDim.x;
    #pragma unroll
    for (int it = 0; it < 4; it++) {
        int i = base + it * stride;
        const float* src; uint32_t* dst; int li, sh, nmask;
        if (i < 4*R1) {
            int r = i >> 17;
            li = i & (R1 - 1);
            src = (r==0) ? wq : (r==1) ? wk : (r==2) ? wv : wo;
            dst = g_wpack + (size_t)r * (NW1/2);
            sh = 10; nmask = DD - 1;
        } else {
            int j = i - 4*R1;
            int r = (j >= 2*RF) ? 2 : (j >= RF ? 1 : 0);
            li = j - r*RF;
            src = (r==0) ? wg : (r==1) ? wu : wd;
            dst = g_wpack + 4*(size_t)(NW1/2) + (size_t)r*(NWF/2);
            if (r == 2) { sh = 10; nmask = DD - 1; }
            else        { sh = 12; nmask = FF - 1; }
        }
        int flat = li * 4;
        int k2 = flat >> sh;
        int n0 = flat & nmask;
        int N = nmask + 1;
        float4 r0 = *(const float4*)&src[(size_t)(2*k2    )*N + n0];
        float4 r1 = *(const float4*)&src[(size_t)(2*k2 + 1)*N + n0];
        uint4 o;
        o.x = pack_bf2(r0.x, r1.x);
        o.y = pack_bf2(r0.y, r1.y);
        o.z = pack_bf2(r0.z, r1.z);
        o.w = pack_bf2(r0.w, r1.w);
        *(uint4*)&dst[(size_t)k2*N + n0] = o;
    }
}

// ---------------- router logits --------------------------------------------
__global__ void router_kernel(const float* __restrict__ hs, const float* __restrict__ wr) {
    int warp = (blockIdx.x * blockDim.x + threadIdx.x) >> 5;
    int lane = threadIdx.x & 31;
    if (warp >= BT) return;
    const float4* row = (const float4*)(hs + (size_t)warp * DD);
    const float4* w   = (const float4*)wr;
    float s = 0.f;
    #pragma unroll
    for (int it = 0; it < 8; it++) {
        float4 a = row[lane + 32 * it];
        float4 b = w[lane + 32 * it];
        s += a.x*b.x + a.y*b.y + a.z*b.z + a.w*b.w;
    }
    #pragma unroll
    for (int o = 16; o; o >>= 1) s += __shfl_down_sync(0xffffffffu, s, o);
    if (lane == 0) g_logits[warp] = s;
}

// ---------------- top-k: radix select + bitmap emit ---------------------------
__global__ void topk_kernel() {
    __shared__ uint32_t keys[TT];
    __shared__ int hist[256];
    __shared__ uint32_t gt_bm[128], eq_bm[128], sel_bm[128];
    __shared__ int epre[128], spre[128];
    __shared__ uint32_t s_prefix;
    __shared__ int s_need;
    int b = blockIdx.x, tid = threadIdx.x;

    for (int i = tid; i < TT; i += 1024) {
        uint32_t u = __float_as_uint(g_logits[b*TT + i]);
        keys[i] = (u & 0x80000000u) ? ~u : (u | 0x80000000u);
    }
    if (tid == 0) { s_prefix = 0u; s_need = KK; }
    if (tid < 128) { gt_bm[tid] = 0u; eq_bm[tid] = 0u; }
    __syncthreads();

    for (int shift = 24; shift >= 0; shift -= 8) {
        if (tid < 256) hist[tid] = 0;
        __syncthreads();
        uint32_t pfx = s_prefix;
        uint32_t pmask = (shift == 24) ? 0u : (0xFFFFFFFFu << (shift + 8));
        for (int i = tid; i < TT; i += 1024) {
            uint32_t k2 = keys[i];
            if ((k2 & pmask) == pfx)
                atomicAdd(&hist[(k2 >> shift) & 255], 1);
        }
        __syncthreads();
        if (tid < 32) {
            int need = s_need;
            int loc[8], lsum = 0;
            #pragma unroll
            for (int j = 0; j < 8; j++) { loc[j] = hist[tid*8 + j]; lsum += loc[j]; }
            int inc = lsum;
            #pragma unroll
            for (int o = 1; o < 32; o <<= 1) {
                int n = __shfl_up_sync(0xffffffffu, inc, o);
                if (tid >= o) inc += n;
            }
            int total = __shfl_sync(0xffffffffu, inc, 31);
            int run = inc - lsum;
            int bestb = -1, bestacc = 0;
            #pragma unroll
            for (int j = 0; j < 8; j++) {
                int cnt_lt = run; run += loc[j];
                if (loc[j] > 0 && total - cnt_lt >= need) {
                    bestb = tid*8 + j;
                    bestacc = total - cnt_lt - loc[j];
                }
            }
            #pragma unroll
            for (int o = 16; o; o >>= 1) {
                int ob = __shfl_down_sync(0xffffffffu, bestb, o);
                int oa = __shfl_down_sync(0xffffffffu, bestacc, o);
                if (ob > bestb) { bestb = ob; bestacc = oa; }
            }
            if (tid == 0) {
                s_need = need - bestacc;
                s_prefix = pfx | ((uint32_t)bestb << shift);
            }
        }
        __syncthreads();
    }

    uint32_t T = s_prefix;
    int need_eq = s_need;

    for (int i = tid; i < TT; i += 1024) {
        uint32_t k2 = keys[i];
        if (k2 > T)       atomicOr(&gt_bm[i >> 5], 1u << (i & 31));
        else if (k2 == T) atomicOr(&eq_bm[i >> 5], 1u << (i & 31));
    }
    __syncthreads();

    if (tid < 32) {
        int el[4], es = 0;
        #pragma unroll
        for (int j = 0; j < 4; j++) { el[j] = __popc(eq_bm[tid*4 + j]); es += el[j]; }
        int ei = es;
        #pragma unroll
        for (int o = 1; o < 32; o <<= 1) {
            int ne = __shfl_up_sync(0xffffffffu, ei, o);
            if (tid >= o) ei += ne;
        }
        int erun = ei - es;
        #pragma unroll
        for (int j = 0; j < 4; j++) { epre[tid*4 + j] = erun; erun += el[j]; }
    }
    __syncthreads();

    if (tid < 128) {
        uint32_t eqw = eq_bm[tid];
        int ep = epre[tid];
        uint32_t accm = 0u;
        if (ep < need_eq) {
            int take = need_eq - ep;
            int pc = __popc(eqw);
            if (take >= pc) accm = eqw;
            else {
                uint32_t m = eqw;
                for (int z = pc - take; z > 0; z--)
                    m &= ~(0x80000000u >> __clz(m));
                accm = m;
            }
        }
        sel_bm[tid] = gt_bm[tid] | accm;
    }
    __syncthreads();

    if (tid < 32) {
        int sl[4], ss = 0;
        #pragma unroll
        for (int j = 0; j < 4; j++) { sl[j] = __popc(sel_bm[tid*4 + j]); ss += sl[j]; }
        int si = ss;
        #pragma unroll
        for (int o = 1; o < 32; o <<= 1) {
            int n = __shfl_up_sync(0xffffffffu, si, o);
            if (tid >= o) si += n;
        }
        int srun = si - ss;
        #pragma unroll
        for (int j = 0; j < 4; j++) { spre[tid*4 + j] = srun; srun += sl[j]; }
    }
    __syncthreads();

    if (tid < 128) {
        uint32_t w = sel_bm[tid];
        int pos = spre[tid];
        while (w) {
            int bit = __ffs(w) - 1;
            w &= w - 1;
            int idx = tid*32 + bit;
            g_idx[b*KK + pos] = idx;
            float l = g_logits[b*TT + idx];
            g_gates[b*KK + pos] = 1.f / (1.f + expf(-l));
            pos++;
        }
    }
}

// ---------------- aux loss -----------------------------------------------------
__global__ void aux1_kernel() {
    __shared__ float red[32];
    float s = 0.f;
    for (int i = blockIdx.x * blockDim.x + threadIdx.x; i < BT; i += gridDim.x * blockDim.x) {
        float l = g_logits[i];
        s += fmaxf(l, 0.f) + log1pf(expf(-fabsf(l)));
    }
    float tot = blk_sum(s, red);
    if (threadIdx.x == 0) g_auxp[blockIdx.x] = tot;
}

__global__ void aux2_kernel(float* __restrict__ out, int aux_off) {
    __shared__ float red[32];
    float s = 0.f;
    if (threadIdx.x < 64) s = g_auxp[threadIdx.x];
    for (int i = threadIdx.x; i < BKr; i += blockDim.x) {
        int b = i >> 9;
        s -= g_logits[b*TT + g_idx[i]];
    }
    float tot = blk_sum(s, red);
    if (threadIdx.x == 0) out[aux_off] = tot * (0.01f / (float)BT);
}

// ---------------- gather + rmsnorm1 -> bf16 ---------------------------------
__global__ void gather_rms1(const float* __restrict__ hs, const float* __restrict__ ln1) {
    __shared__ float red[32];
    int bj = blockIdx.x;
    int b = bj >> 9;
    int row = g_idx[bj];
    const float4* src = (const float4*)(hs + ((size_t)(b*TT + row)) * DD);
    float4 x = src[threadIdx.x];
    float ss = x.x*x.x + x.y*x.y + x.z*x.z + x.w*x.w;
    float tot = blk_sum(ss, red);
    float r = rsqrtf(tot / (float)DD + 1e-6f);
    ((float4*)g_xsel)[bj*256 + threadIdx.x] = x;
    float4 w = ((const float4*)ln1)[threadIdx.x];
    uint32_t lo = pack_bf2(x.x*r*w.x, x.y*r*w.y);
    uint32_t hi = pack_bf2(x.z*r*w.z, x.w*r*w.w);
    *(uint2*)&g_hb[(size_t)bj*DD + threadIdx.x*4] = make_uint2(lo, hi);
}

// ---------------- combine wo split-K partials + rmsnorm2 -> bf16 -------------
__global__ void combine_rms2(const float* __restrict__ ln2) {
    __shared__ float red[32];
    int bj = blockIdx.x;
    int i = bj*256 + threadIdx.x;
    float4 xs = ((const float4*)g_xsel)[i];
    float4 p0 = ((const float4*)g_q)[i];
    float4 p1 = ((const float4*)g_k)[i];
    float4 x = make_float4(xs.x + p0.x + p1.x, xs.y + p0.y + p1.y,
                           xs.z + p0.z + p1.z, xs.w + p0.w + p1.w);
    ((float4*)g_x1)[i] = x;
    float ss = x.x*x.x + x.y*x.y + x.z*x.z + x.w*x.w;
    float tot = blk_sum(ss, red);
    float r = rsqrtf(tot / (float)DD + 1e-6f);
    float4 w = ((const float4*)ln2)[threadIdx.x];
    uint32_t lo = pack_bf2(x.x*r*w.x, x.y*r*w.y);
    uint32_t hi = pack_bf2(x.z*r*w.z, x.w*r*w.w);
    *(uint2*)&g_h2b[(size_t)bj*DD + threadIdx.x*4] = make_uint2(lo, hi);
}

// ---------------- BF16 tensor-core GEMM (2-stage cp.async, split-K) -----------
// out_mode: 0 = fp32, 1 = fp32 tf32-rounded, 5 = QKV (rope fused for z<2, rnd)
#define ASTR 20
#define BSTR 136
__global__ __launch_bounds__(256) void gemm_bf(
    const __nv_bfloat16* __restrict__ A,
    const uint32_t* __restrict__ B0, const uint32_t* __restrict__ B1, const uint32_t* __restrict__ B2,
    float* __restrict__ C0, float* __restrict__ C1, float* __restrict__ C2,
    int M, int N, int Ktot, int Klen, int koff_step, int out_mode)
{
    const uint32_t* B = (blockIdx.z == 0) ? B0 : (blockIdx.z == 1 ? B1 : B2);
    float*          C = (blockIdx.z == 0) ? C0 : (blockIdx.z == 1 ? C1 : C2);
    int kbase = (blockIdx.z * koff_step) >> 1;

    __shared__ uint32_t As[2][128][ASTR];
    __shared__ uint32_t Bs[2][16][BSTR];
    int tid = threadIdx.x;
    int w = tid >> 5, lane = tid & 31;
    int wm = w >> 1, wn = w & 1;
    int gid = lane >> 2, tid4 = lane & 3;
    int row0 = blockIdx.y * 128, col0 = blockIdx.x * 128;

    const uint32_t* Au = (const uint32_t*)A;
    int K2tot = Ktot >> 1;

    int arr = tid >> 1;
    int arc = (tid & 1) * 8;
    int brw = tid >> 4;
    int bcc = (tid & 15) * 4;

    float acc[2][8][4];
    #pragma unroll
    for (int i = 0; i < 2; i++)
        #pragma unroll
        for (int j = 0; j < 8; j++)
            #pragma unroll
            for (int c = 0; c < 4; c++) acc[i][j][c] = 0.f;

    int nt = Klen / 32;

    cp16(&As[0][arr][arc],     &Au[(size_t)(row0 + arr)*K2tot + kbase + arc]);
    cp16(&As[0][arr][arc + 4], &Au[(size_t)(row0 + arr)*K2tot + kbase + arc + 4]);
    cp16(&Bs[0][brw][bcc],      &B[(size_t)(kbase + brw)*N + col0 + bcc]);
    cp16(&Bs[0][brw][bcc + 64], &B[(size_t)(kbase + brw)*N + col0 + bcc + 64]);
    asm volatile("cp.async.commit_group;");

    int buf = 0;
    for (int t = 0; t < nt; t++) {
        if (t + 1 < nt) {
            int k2o = kbase + (t + 1) * 16;
            cp16(&As[buf^1][arr][arc],     &Au[(size_t)(row0 + arr)*K2tot + k2o + arc]);
            cp16(&As[buf^1][arr][arc + 4], &Au[(size_t)(row0 + arr)*K2tot + k2o + arc + 4]);
            cp16(&Bs[buf^1][brw][bcc],      &B[(size_t)(k2o + brw)*N + col0 + bcc]);
            cp16(&Bs[buf^1][brw][bcc + 64], &B[(size_t)(k2o + brw)*N + col0 + bcc + 64]);
            asm volatile("cp.async.commit_group;");
            asm volatile("cp.async.wait_group 1;");
        } else {
            asm volatile("cp.async.wait_group 0;");
        }
        __syncthreads();

        #pragma unroll
        for (int ks = 0; ks < 2; ks++) {
            int kb = ks * 8;
            uint32_t af[2][4];
            #pragma unroll
            for (int mt = 0; mt < 2; mt++) {
                int rm = wm*32 + mt*16;
                af[mt][0] = As[buf][rm + gid    ][kb + tid4    ];
                af[mt][1] = As[buf][rm + gid + 8][kb + tid4    ];
                af[mt][2] = As[buf][rm + gid    ][kb + tid4 + 4];
                af[mt][3] = As[buf][rm + gid + 8][kb + tid4 + 4];
            }
            #pragma unroll
            for (int n2 = 0; n2 < 8; n2++) {
                int cn = wn*64 + n2*8 + gid;
                uint32_t b0 = Bs[buf][kb + tid4    ][cn];
                uint32_t b1 = Bs[buf][kb + tid4 + 4][cn];
                MMA_BF16(acc[0][n2][0], acc[0][n2][1], acc[0][n2][2], acc[0][n2][3],
                         af[0][0], af[0][1], af[0][2], af[0][3], b0, b1);
                MMA_BF16(acc[1][n2][0], acc[1][n2][1], acc[1][n2][2], acc[1][n2][3],
                         af[1][0], af[1][1], af[1][2], af[1][3], b0, b1);
            }
        }
        __syncthreads();
        buf ^= 1;
    }

    if (out_mode == 5) {
        bool dorope = (blockIdx.z < 2);
        #pragma unroll
        for (int mt = 0; mt < 2; mt++) {
            int row = row0 + wm*32 + mt*16 + gid;
            float posA = 0.f, posB = 0.f;
            if (dorope) {
                posA = (float)g_idx[row];
                posB = (float)g_idx[row + 8];
            }
            #pragma unroll
            for (int n2 = 0; n2 < 4; n2++) {
                int col = col0 + wn*64 + n2*8 + tid4*2;
                float x1a = acc[mt][n2][0],   x1b = acc[mt][n2][1];
                float x1c = acc[mt][n2][2],   x1d = acc[mt][n2][3];
                float x2a = acc[mt][n2+4][0], x2b = acc[mt][n2+4][1];
                float x2c = acc[mt][n2+4][2], x2d = acc[mt][n2+4][3];
                float o1a, o1b, o1c, o1d, o2a, o2b, o2c, o2d;
                if (dorope) {
                    int d0 = col & 63;
                    float inv0 = expf(-logf(10000.f) * (float)d0 / 32.f);
                    float inv1 = expf(-logf(10000.f) * (float)(d0 + 1) / 32.f);
                    float cA0, sA0, cA1, sA1, cB0, sB0, cB1, sB1;
                    __sincosf(posA * inv0, &sA0, &cA0);
                    __sincosf(posA * inv1, &sA1, &cA1);
                    __sincosf(posB * inv0, &sB0, &cB0);
                    __sincosf(posB * inv1, &sB1, &cB1);
                    o1a = x1a*cA0 - x2a*sA0;  o2a = x2a*cA0 + x1a*sA0;
                    o1b = x1b*cA1 - x2b*sA1;  o2b = x2b*cA1 + x1b*sA1;
                    o1c = x1c*cB0 - x2c*sB0;  o2c = x2c*cB0 + x1c*sB0;
                    o1d = x1d*cB1 - x2d*sB1;  o2d = x2d*cB1 + x1d*sB1;
                } else {
                    o1a = x1a; o1b = x1b; o1c = x1c; o1d = x1d;
                    o2a = x2a; o2b = x2b; o2c = x2c; o2d = x2d;
                }
                *(float2*)&C[(size_t)row*N + col]          = make_float2(rnd(o1a), rnd(o1b));
                *(float2*)&C[(size_t)(row+8)*N + col]      = make_float2(rnd(o1c), rnd(o1d));
                *(float2*)&C[(size_t)row*N + col + 32]     = make_float2(rnd(o2a), rnd(o2b));
                *(float2*)&C[(size_t)(row+8)*N + col + 32] = make_float2(rnd(o2c), rnd(o2d));
            }
        }
    } else {
        #pragma unroll
        for (int mt = 0; mt < 2; mt++) {
            int row = row0 + wm*32 + mt*16 + gid;
            #pragma unroll
            for (int n2 = 0; n2 < 8; n2++) {
                int col = col0 + wn*64 + n2*8 + tid4*2;
                float2 v0 = make_float2(acc[mt][n2][0], acc[mt][n2][1]);
                float2 v1 = make_float2(acc[mt][n2][2], acc[mt][n2][3]);
                if (out_mode == 1) {
                    v0.x = rnd(v0.x); v0.y = rnd(v0.y);
                    v1.x = rnd(v1.x); v1.y = rnd(v1.y);
                }
                *(float2*)&C[(size_t)row*N + col]     = v0;
                *(float2*)&C[(size_t)(row+8)*N + col] = v1;
            }
        }
    }
}

// ---------------- tf32 flash attention, bf16 output, heavy-first --------------
__global__ __launch_bounds__(128) void attn_tc() {
    __shared__ float Qs[64][68];
    __shared__ float Ks[64][68];
    __shared__ float Vs[64][72];
    __shared__ float Ps[4][16][68];
    int qt = gridDim.x - 1 - blockIdx.x;
    int h = blockIdx.y, b = blockIdx.z;
    int tid = threadIdx.x, w = tid >> 5, lane = tid & 31;
    int gid = lane >> 2, tid4 = lane & 3;

    for (int f = tid; f < 64*16; f += 128) {
        int q = f >> 4, d4 = (f & 15) << 2;
        *(float4*)&Qs[q][d4] =
            *(const float4*)&g_q[((size_t)((b*KK + qt*64 + q)*HEADS + h))*HDIM + d4];
    }

    int r0g = qt*64 + w*16 + gid;
    int r1g = r0g + 8;

    float m0 = -1e30f, m1 = -1e30f, l0 = 0.f, l1 = 0.f;
    float oa[8][4];
    #pragma unroll
    for (int n2 = 0; n2 < 8; n2++)
        #pragma unroll
        for (int c = 0; c < 4; c++) oa[n2][c] = 0.f;

    for (int kt = 0; kt <= qt; kt++) {
        __syncthreads();
        for (int f = tid; f < 64*16; f += 128) {
            int k = f >> 4, d4 = (f & 15) << 2;
            size_t base = ((size_t)((b*KK + kt*64 + k)*HEADS + h))*HDIM + d4;
            *(float4*)&Ks[k][d4] = *(const float4*)&g_k[base];
            *(float4*)&Vs[k][d4] = *(const float4*)&g_v[base];
        }
        __syncthreads();

        float sc[8][4];
        #pragma unroll
        for (int n2 = 0; n2 < 8; n2++)
            #pragma unroll
            for (int c = 0; c < 4; c++) sc[n2][c] = 0.f;

        #pragma unroll
        for (int ks = 0; ks < 8; ks++) {
            int kb = ks * 8;
            uint32_t a0 = __float_as_uint(Qs[w*16 + gid    ][kb + tid4    ]);
            uint32_t a1 = __float_as_uint(Qs[w*16 + gid + 8][kb + tid4    ]);
            uint32_t a2 = __float_as_uint(Qs[w*16 + gid    ][kb + tid4 + 4]);
            uint32_t a3 = __float_as_uint(Qs[w*16 + gid + 8][kb + tid4 + 4]);
            #pragma unroll
            for (int n2 = 0; n2 < 8; n2++) {
                uint32_t b0 = __float_as_uint(Ks[n2*8 + gid][kb + tid4    ]);
                uint32_t b1 = __float_as_uint(Ks[n2*8 + gid][kb + tid4 + 4]);
                MMA_TF32(sc[n2][0], sc[n2][1], sc[n2][2], sc[n2][3],
                         a0, a1, a2, a3, b0, b1);
            }
        }

        bool diag = (kt == qt);
        float mx0 = -1e30f, mx1 = -1e30f;
        #pragma unroll
        for (int n2 = 0; n2 < 8; n2++) {
            int col = kt*64 + n2*8 + 2*tid4;
            sc[n2][0] *= 0.125f; sc[n2][1] *= 0.125f;
            sc[n2][2] *= 0.125f; sc[n2][3] *= 0.125f;
            if (diag) {
                if (col     > r0g) sc[n2][0] = -1e30f;
                if (col + 1 > r0g) sc[n2][1] = -1e30f;
                if (col     > r1g) sc[n2][2] = -1e30f;
                if (col + 1 > r1g) sc[n2][3] = -1e30f;
            }
            mx0 = fmaxf(mx0, fmaxf(sc[n2][0], sc[n2][1]));
            mx1 = fmaxf(mx1, fmaxf(sc[n2][2], sc[n2][3]));
        }
        #pragma unroll
        for (int o = 1; o <= 2; o <<= 1) {
            mx0 = fmaxf(mx0, __shfl_xor_sync(0xffffffffu, mx0, o));
            mx1 = fmaxf(mx1, __shfl_xor_sync(0xffffffffu, mx1, o));
        }
        float mn0 = fmaxf(m0, mx0), mn1 = fmaxf(m1, mx1);
        float cor0 = __expf(m0 - mn0), cor1 = __expf(m1 - mn1);
        m0 = mn0; m1 = mn1;
        float rs0 = 0.f, rs1 = 0.f;
        #pragma unroll
        for (int n2 = 0; n2 < 8; n2++) {
            float p0 = __expf(sc[n2][0] - mn0);
            float p1 = __expf(sc[n2][1] - mn0);
            float p2 = __expf(sc[n2][2] - mn1);
            float p3 = __expf(sc[n2][3] - mn1);
            rs0 += p0 + p1; rs1 += p2 + p3;
            *(float2*)&Ps[w][gid    ][n2*8 + 2*tid4] = make_float2(rnd(p0), rnd(p1));
            *(float2*)&Ps[w][gid + 8][n2*8 + 2*tid4] = make_float2(rnd(p2), rnd(p3));
        }
        #pragma unroll
        for (int o = 1; o <= 2; o <<= 1) {
            rs0 += __shfl_xor_sync(0xffffffffu, rs0, o);
            rs1 += __shfl_xor_sync(0xffffffffu, rs1, o);
        }
        l0 = l0 * cor0 + rs0;
        l1 = l1 * cor1 + rs1;
        #pragma unroll
        for (int n2 = 0; n2 < 8; n2++) {
            oa[n2][0] *= cor0; oa[n2][1] *= cor0;
            oa[n2][2] *= cor1; oa[n2][3] *= cor1;
        }
        __syncwarp();

        #pragma unroll
        for (int ks = 0; ks < 8; ks++) {
            uint32_t a0 = __float_as_uint(Ps[w][gid    ][ks*8 + tid4    ]);
            uint32_t a1 = __float_as_uint(Ps[w][gid + 8][ks*8 + tid4    ]);
            uint32_t a2 = __float_as_uint(Ps[w][gid    ][ks*8 + tid4 + 4]);
            uint32_t a3 = __float_as_uint(Ps[w][gid + 8][ks*8 + tid4 + 4]);
            #pragma unroll
            for (int n2 = 0; n2 < 8; n2++) {
                uint32_t b0 = __float_as_uint(Vs[ks*8 + tid4    ][n2*8 + gid]);
                uint32_t b1 = __float_as_uint(Vs[ks*8 + tid4 + 4][n2*8 + gid]);
                MMA_TF32(oa[n2][0], oa[n2][1], oa[n2][2], oa[n2][3],
                         a0, a1, a2, a3, b0, b1);
            }
        }
        __syncwarp();
    }

    float i0 = 1.f / l0, i1 = 1.f / l1;
    #pragma unroll
    for (int n2 = 0; n2 < 8; n2++) {
        int d = n2*8 + 2*tid4;
        uint32_t p0 = pack_bf2(oa[n2][0]*i0, oa[n2][1]*i0);
        uint32_t p1 = pack_bf2(oa[n2][2]*i1, oa[n2][3]*i1);
        *(uint32_t*)&g_ob[((size_t)((b*KK + r0g)*HEADS + h))*HDIM + d] = p0;
        *(uint32_t*)&g_ob[((size_t)((b*KK + r1g)*HEADS + h))*HDIM + d] = p1;
    }
}

// ---------------- silu(gate)*up -> bf16 --------------------------------------
__global__ void silu_mul_kernel() {
    int i = blockIdx.x * blockDim.x + threadIdx.x;
    const int N4 = BKr*FF/4;
    if (i >= N4) return;
    float4 g = ((const float4*)g_gateb)[i];
    float4 u = ((const float4*)g_upb)[i];
    float a = g.x / (1.f + __expf(-g.x)) * u.x;
    float b = g.y / (1.f + __expf(-g.y)) * u.y;
    float c = g.z / (1.f + __expf(-g.z)) * u.z;
    float d = g.w / (1.f + __expf(-g.w)) * u.w;
    *(uint2*)&g_mlpa[(size_t)i*4] = make_uint2(pack_bf2(a, b), pack_bf2(c, d));
}

// ---------------- scatter: combine down split-K + gated residual --------------
__global__ void scatter_kernel(float* __restrict__ out) {
    int bj = blockIdx.x;
    int b = bj >> 9;
    int row = g_idx[bj];
    float gate = g_gates[bj];
    int i = bj*256 + threadIdx.x;
    float4 xs = ((const float4*)g_xsel)[i];
    float4 x1 = ((const float4*)g_x1)[i];
    float4 p0 = ((const float4*)g_q)[i];
    float4 p1 = ((const float4*)g_k)[i];
    float4 o;
    o.x = xs.x + gate*((x1.x + p0.x + p1.x) - xs.x);
    o.y = xs.y + gate*((x1.y + p0.y + p1.y) - xs.y);
    o.z = xs.z + gate*((x1.z + p0.z + p1.z) - xs.z);
    o.w = xs.w + gate*((x1.w + p0.w + p1.w) - xs.w);
    ((float4*)out)[((size_t)(b*TT + row))*256 + threadIdx.x] = o;
}

// ---------------- launch -------------------------------------------------------
extern "C" void kernel_launch(void* const* d_in, const int* in_sizes, int n_in,
                              void* d_out, int out_size) {
    const float* hs  = (const float*)d_in[0];
    const float* wr  = (const float*)d_in[1];
    const float* wq  = (const float*)d_in[2];
    const float* wk  = (const float*)d_in[3];
    const float* wv  = (const float*)d_in[4];
    const float* wo  = (const float*)d_in[5];
    const float* ln1 = (const float*)d_in[6];
    const float* ln2 = (const float*)d_in[7];
    const float* wg  = (const float*)d_in[8];
    const float* wu  = (const float*)d_in[9];
    const float* wd  = (const float*)d_in[10];
    float* out = (float*)d_out;

    static cudaStream_t s2 = nullptr;
    static cudaEvent_t evA = nullptr, evB = nullptr, evC = nullptr, evD = nullptr;
    if (!s2) {
        cudaStreamCreateWithFlags(&s2, cudaStreamNonBlocking);
        cudaEventCreateWithFlags(&evA, cudaEventDisableTiming);
        cudaEventCreateWithFlags(&evB, cudaEventDisableTiming);
        cudaEventCreateWithFlags(&evC, cudaEventDisableTiming);
        cudaEventCreateWithFlags(&evD, cudaEventDisableTiming);
    }

    float *p_q, *p_k, *p_v, *p_gate, *p_up;
    __nv_bfloat16 *p_hb, *p_ob, *p_h2b, *p_mlpa;
    uint32_t *p_wp;
    cudaGetSymbolAddress((void**)&p_q,    g_q);
    cudaGetSymbolAddress((void**)&p_k,    g_k);
    cudaGetSymbolAddress((void**)&p_v,    g_v);
    cudaGetSymbolAddress((void**)&p_gate, g_gateb);
    cudaGetSymbolAddress((void**)&p_up,   g_upb);
    cudaGetSymbolAddress((void**)&p_hb,   g_hb);
    cudaGetSymbolAddress((void**)&p_ob,   g_ob);
    cudaGetSymbolAddress((void**)&p_h2b,  g_h2b);
    cudaGetSymbolAddress((void**)&p_mlpa, g_mlpa);
    cudaGetSymbolAddress((void**)&p_wp,   g_wpack);

    uint32_t* rwq = p_wp;
    uint32_t* rwk = p_wp + NW1/2;
    uint32_t* rwv = p_wp + 2*(NW1/2);
    uint32_t* rwo = p_wp + 3*(NW1/2);
    uint32_t* rwg = p_wp + 4*(NW1/2);
    uint32_t* rwu = p_wp + 4*(NW1/2) + NWF/2;
    uint32_t* rwd = p_wp + 4*(NW1/2) + 2*(NWF/2);

    // fork: side stream packs weights first (QKV joins on evB).
    cudaEventRecord(evA, 0);
    cudaStreamWaitEvent(s2, evA, 0);
    pack_all<<<2048, 256, 0, s2>>>(wq, wk, wv, wo, wg, wu, wd);
    cudaEventRecord(evB, s2);

    // main front chain: router -> topk -> gather (aux1 off the critical path)
    router_kernel<<<BT/8, 256>>>(hs, wr);
    topk_kernel<<<BB, 1024>>>();
    gather_rms1<<<BKr, 256>>>(hs, ln1);
    aux1_kernel<<<64, 256>>>();

    cudaStreamWaitEvent(0, evB, 0);

    // fused QKV with in-epilogue RoPE (q,k) + tf32 rounding
    gemm_bf<<<dim3(DD/128, BKr/128, 3), 256>>>(p_hb, rwq, rwk, rwv,
                                               p_q, p_k, p_v,
                                               BKr, DD, DD, DD, 0, 5);
    cudaEventRecord(evD, 0);

    // side stream: copy hidden->out only AFTER the DRAM-hungry QKV completes;
    // it then overlaps the smem/tensor-bound attention + MLP phase.
    cudaStreamWaitEvent(s2, evD, 0);
    cudaMemcpyAsync(out, hs, (size_t)BT*DD*sizeof(float), cudaMemcpyDeviceToDevice, s2);
    cudaEventRecord(evC, s2);

    // aux2 off the critical path: overlaps with QKV tail
    aux2_kernel<<<1, 1024>>>(out, out_size - 1);

    attn_tc<<<dim3(KK/64, HEADS, BB), 128>>>();

    // wo: split-K x2 into g_q/g_k partials
    gemm_bf<<<dim3(DD/128, BKr/128, 2), 256>>>(p_ob, rwo, rwo, rwo,
                                               p_q, p_k, p_k,
                                               BKr, DD, DD, DD/2, DD/2, 0);
    combine_rms2<<<BKr, 256>>>(ln2);

    // gate/up fused
    gemm_bf<<<dim3(FF/128, BKr/128, 2), 256>>>(p_h2b, rwg, rwu, rwu,
                                               p_gate, p_up, p_up,
                                               BKr, FF, DD, DD, 0, 0);
    silu_mul_kernel<<<(BKr*FF/4 + 255)/256, 256>>>();

    // down: split-K x2 into g_q/g_k partials
    gemm_bf<<<dim3(DD/128, BKr/128, 2), 256>>>(p_mlpa, rwd, rwd, rwd,
                                               p_q, p_k, p_k,
                                               BKr, DD, FF, FF/2, FF/2, 0);

    // join the out-copy right before the scatter that overwrites selected rows
    cudaStreamWaitEvent(0, evC, 0);
    scatter_kernel<<<BKr, 256>>>(out);
}

// round 17
// speedup vs baseline: 1.0255x; 1.0246x over previous
#include <cuda_runtime.h>
#include <cuda_bf16.h>
#include <math.h>
#include <stdint.h>

#define BB 4
#define TT 4096
#define DD 1024
#define HEADS 16
#define HDIM 64
#define FF 4096
#define KK 512
#define BT (BB*TT)      // 16384
#define BKr (BB*KK)     // 2048

#define NW1 (DD*DD)
#define NWF (DD*FF)

// ---------------- scratch ----------------------------------------------------
__device__ float g_logits[BT];
__device__ float g_auxp[64];
__device__ int   g_idx[BKr];
__device__ float g_gates[BKr];
__device__ float g_xsel[BKr*DD];
__device__ float g_q[BKr*DD];      // qkv q; later split-K partial 0
__device__ float g_k[BKr*DD];      // qkv k; later split-K partial 1
__device__ float g_v[BKr*DD];
__device__ float g_x1[BKr*DD];
__device__ float g_gateb[BKr*FF];
__device__ float g_upb[BKr*FF];
__device__ __nv_bfloat16 g_hb[BKr*DD];
__device__ __nv_bfloat16 g_ob[BKr*DD];
__device__ __nv_bfloat16 g_h2b[BKr*DD];
__device__ __nv_bfloat16 g_mlpa[BKr*FF];
__device__ uint32_t g_wpack[(4*NW1 + 3*NWF)/2];

// ---------------- helpers ----------------------------------------------------
__device__ __forceinline__ float blk_sum(float v, float* red) {
    int lane = threadIdx.x & 31, w = threadIdx.x >> 5;
    #pragma unroll
    for (int o = 16; o; o >>= 1) v += __shfl_down_sync(0xffffffffu, v, o);
    if (lane == 0) red[w] = v;
    __syncthreads();
    int nw = (blockDim.x + 31) >> 5;
    if (threadIdx.x < 32) {
        float t = (threadIdx.x < nw) ? red[threadIdx.x] : 0.f;
        #pragma unroll
        for (int o = 16; o; o >>= 1) t += __shfl_down_sync(0xffffffffu, t, o);
        if (threadIdx.x == 0) red[0] = t;
    }
    __syncthreads();
    float r = red[0];
    __syncthreads();
    return r;
}

__device__ __forceinline__ uint32_t f2tf(float x) {
    uint32_t y;
    asm("cvt.rna.tf32.f32 %0, %1;" : "=r"(y) : "f"(x));
    return y;
}
__device__ __forceinline__ float rnd(float x) { return __uint_as_float(f2tf(x)); }

__device__ __forceinline__ uint32_t pack_bf2(float lo, float hi) {
    __nv_bfloat162 t = __floats2bfloat162_rn(lo, hi);
    return *(uint32_t*)&t;
}

__device__ __forceinline__ void cp16(void* s, const void* g) {
    uint32_t sa = (uint32_t)__cvta_generic_to_shared(s);
    asm volatile("cp.async.cg.shared.global [%0], [%1], 16;" :: "r"(sa), "l"(g));
}

#define MMA_BF16(d0,d1,d2,d3,a0,a1,a2,a3,b0,b1) \
    asm volatile("mma.sync.aligned.m16n8k16.row.col.f32.bf16.bf16.f32 " \
        "{%0,%1,%2,%3}, {%4,%5,%6,%7}, {%8,%9}, {%0,%1,%2,%3};" \
        : "+f"(d0), "+f"(d1), "+f"(d2), "+f"(d3) \
        : "r"(a0), "r"(a1), "r"(a2), "r"(a3), "r"(b0), "r"(b1))

#define MMA_TF32(d0,d1,d2,d3,a0,a1,a2,a3,b0,b1) \
    asm volatile("mma.sync.aligned.m16n8k8.row.col.f32.tf32.tf32.f32 " \
        "{%0,%1,%2,%3}, {%4,%5,%6,%7}, {%8,%9}, {%0,%1,%2,%3};" \
        : "+f"(d0), "+f"(d1), "+f"(d2), "+f"(d3) \
        : "r"(a0), "r"(a1), "r"(a2), "r"(a3), "r"(b0), "r"(b1))

// ---------------- fused weight pack ------------------------------------------
__global__ void pack_all(const float* __restrict__ wq, const float* __restrict__ wk,
                         const float* __restrict__ wv, const float* __restrict__ wo,
                         const float* __restrict__ wg, const float* __restrict__ wu,
                         const float* __restrict__ wd) {
    const int R1 = NW1/8;
    const int RF = NWF/8;
    int base = blockIdx.x * blockDim.x + threadIdx.x;
    int stride = gridDim.x * blockDim.x;
    #pragma unroll
    for (int it = 0; it < 4; it++) {
        int i = base + it * stride;
        const float* src; uint32_t* dst; int li, sh, nmask;
        if (i < 4*R1) {
            int r = i >> 17;
            li = i & (R1 - 1);
            src = (r==0) ? wq : (r==1) ? wk : (r==2) ? wv : wo;
            dst = g_wpack + (size_t)r * (NW1/2);
            sh = 10; nmask = DD - 1;
        } else {
            int j = i - 4*R1;
            int r = (j >= 2*RF) ? 2 : (j >= RF ? 1 : 0);
            li = j - r*RF;
            src = (r==0) ? wg : (r==1) ? wu : wd;
            dst = g_wpack + 4*(size_t)(NW1/2) + (size_t)r*(NWF/2);
            if (r == 2) { sh = 10; nmask = DD - 1; }
            else        { sh = 12; nmask = FF - 1; }
        }
        int flat = li * 4;
        int k2 = flat >> sh;
        int n0 = flat & nmask;
        int N = nmask + 1;
        float4 r0 = *(const float4*)&src[(size_t)(2*k2    )*N + n0];
        float4 r1 = *(const float4*)&src[(size_t)(2*k2 + 1)*N + n0];
        uint4 o;
        o.x = pack_bf2(r0.x, r1.x);
        o.y = pack_bf2(r0.y, r1.y);
        o.z = pack_bf2(r0.z, r1.z);
        o.w = pack_bf2(r0.w, r1.w);
        *(uint4*)&dst[(size_t)k2*N + n0] = o;
    }
}

// ---------------- router logits --------------------------------------------
__global__ void router_kernel(const float* __restrict__ hs, const float* __restrict__ wr) {
    int warp = (blockIdx.x * blockDim.x + threadIdx.x) >> 5;
    int lane = threadIdx.x & 31;
    if (warp >= BT) return;
    const float4* row = (const float4*)(hs + (size_t)warp * DD);
    const float4* w   = (const float4*)wr;
    float s = 0.f;
    #pragma unroll
    for (int it = 0; it < 8; it++) {
        float4 a = row[lane + 32 * it];
        float4 b = w[lane + 32 * it];
        s += a.x*b.x + a.y*b.y + a.z*b.z + a.w*b.w;
    }
    #pragma unroll
    for (int o = 16; o; o >>= 1) s += __shfl_down_sync(0xffffffffu, s, o);
    if (lane == 0) g_logits[warp] = s;
}

// ---------------- top-k: radix select + bitmap emit ---------------------------
// First histogram pass fused into key load (shift=24 has no prefix filter).
__global__ void topk_kernel() {
    __shared__ uint32_t keys[TT];
    __shared__ int hist[256];
    __shared__ uint32_t gt_bm[128], eq_bm[128], sel_bm[128];
    __shared__ int epre[128], spre[128];
    __shared__ uint32_t s_prefix;
    __shared__ int s_need;
    int b = blockIdx.x, tid = threadIdx.x;

    if (tid == 0) { s_prefix = 0u; s_need = KK; }
    if (tid < 128) { gt_bm[tid] = 0u; eq_bm[tid] = 0u; }
    if (tid < 256) hist[tid] = 0;
    __syncthreads();

    // load keys + top-byte histogram in one pass
    for (int i = tid; i < TT; i += 1024) {
        uint32_t u = __float_as_uint(g_logits[b*TT + i]);
        uint32_t k2 = (u & 0x80000000u) ? ~u : (u | 0x80000000u);
        keys[i] = k2;
        atomicAdd(&hist[k2 >> 24], 1);
    }
    __syncthreads();

    for (int shift = 24; shift >= 0; shift -= 8) {
        if (shift < 24) {
            if (tid < 256) hist[tid] = 0;
            __syncthreads();
            uint32_t pfx = s_prefix;
            uint32_t pmask = 0xFFFFFFFFu << (shift + 8);
            for (int i = tid; i < TT; i += 1024) {
                uint32_t k2 = keys[i];
                if ((k2 & pmask) == pfx)
                    atomicAdd(&hist[(k2 >> shift) & 255], 1);
            }
            __syncthreads();
        }
        if (tid < 32) {
            int need = s_need;
            int loc[8], lsum = 0;
            #pragma unroll
            for (int j = 0; j < 8; j++) { loc[j] = hist[tid*8 + j]; lsum += loc[j]; }
            int inc = lsum;
            #pragma unroll
            for (int o = 1; o < 32; o <<= 1) {
                int n = __shfl_up_sync(0xffffffffu, inc, o);
                if (tid >= o) inc += n;
            }
            int total = __shfl_sync(0xffffffffu, inc, 31);
            int run = inc - lsum;
            int bestb = -1, bestacc = 0;
            #pragma unroll
            for (int j = 0; j < 8; j++) {
                int cnt_lt = run; run += loc[j];
                if (loc[j] > 0 && total - cnt_lt >= need) {
                    bestb = tid*8 + j;
                    bestacc = total - cnt_lt - loc[j];
                }
            }
            #pragma unroll
            for (int o = 16; o; o >>= 1) {
                int ob = __shfl_down_sync(0xffffffffu, bestb, o);
                int oa = __shfl_down_sync(0xffffffffu, bestacc, o);
                if (ob > bestb) { bestb = ob; bestacc = oa; }
            }
            if (tid == 0) {
                s_need = need - bestacc;
                s_prefix = s_prefix | ((uint32_t)bestb << shift);
            }
        }
        __syncthreads();
    }

    uint32_t T = s_prefix;
    int need_eq = s_need;

    for (int i = tid; i < TT; i += 1024) {
        uint32_t k2 = keys[i];
        if (k2 > T)       atomicOr(&gt_bm[i >> 5], 1u << (i & 31));
        else if (k2 == T) atomicOr(&eq_bm[i >> 5], 1u << (i & 31));
    }
    __syncthreads();

    if (tid < 32) {
        int el[4], es = 0;
        #pragma unroll
        for (int j = 0; j < 4; j++) { el[j] = __popc(eq_bm[tid*4 + j]); es += el[j]; }
        int ei = es;
        #pragma unroll
        for (int o = 1; o < 32; o <<= 1) {
            int ne = __shfl_up_sync(0xffffffffu, ei, o);
            if (tid >= o) ei += ne;
        }
        int erun = ei - es;
        #pragma unroll
        for (int j = 0; j < 4; j++) { epre[tid*4 + j] = erun; erun += el[j]; }
    }
    __syncthreads();

    if (tid < 128) {
        uint32_t eqw = eq_bm[tid];
        int ep = epre[tid];
        uint32_t accm = 0u;
        if (ep < need_eq) {
            int take = need_eq - ep;
            int pc = __popc(eqw);
            if (take >= pc) accm = eqw;
            else {
                uint32_t m = eqw;
                for (int z = pc - take; z > 0; z--)
                    m &= ~(0x80000000u >> __clz(m));
                accm = m;
            }
        }
        sel_bm[tid] = gt_bm[tid] | accm;
    }
    __syncthreads();

    if (tid < 32) {
        int sl[4], ss = 0;
        #pragma unroll
        for (int j = 0; j < 4; j++) { sl[j] = __popc(sel_bm[tid*4 + j]); ss += sl[j]; }
        int si = ss;
        #pragma unroll
        for (int o = 1; o < 32; o <<= 1) {
            int n = __shfl_up_sync(0xffffffffu, si, o);
            if (tid >= o) si += n;
        }
        int srun = si - ss;
        #pragma unroll
        for (int j = 0; j < 4; j++) { spre[tid*4 + j] = srun; srun += sl[j]; }
    }
    __syncthreads();

    if (tid < 128) {
        uint32_t w = sel_bm[tid];
        int pos = spre[tid];
        while (w) {
            int bit = __ffs(w) - 1;
            w &= w - 1;
            int idx = tid*32 + bit;
            g_idx[b*KK + pos] = idx;
            float l = g_logits[b*TT + idx];
            g_gates[b*KK + pos] = 1.f / (1.f + expf(-l));
            pos++;
        }
    }
}

// ---------------- aux loss -----------------------------------------------------
__global__ void aux1_kernel() {
    __shared__ float red[32];
    float s = 0.f;
    for (int i = blockIdx.x * blockDim.x + threadIdx.x; i < BT; i += gridDim.x * blockDim.x) {
        float l = g_logits[i];
        s += fmaxf(l, 0.f) + log1pf(expf(-fabsf(l)));
    }
    float tot = blk_sum(s, red);
    if (threadIdx.x == 0) g_auxp[blockIdx.x] = tot;
}

__global__ void aux2_kernel(float* __restrict__ out, int aux_off) {
    __shared__ float red[32];
    float s = 0.f;
    if (threadIdx.x < 64) s = g_auxp[threadIdx.x];
    for (int i = threadIdx.x; i < BKr; i += blockDim.x) {
        int b = i >> 9;
        s -= g_logits[b*TT + g_idx[i]];
    }
    float tot = blk_sum(s, red);
    if (threadIdx.x == 0) out[aux_off] = tot * (0.01f / (float)BT);
}

// ---------------- gather + rmsnorm1 -> bf16 ---------------------------------
__global__ void gather_rms1(const float* __restrict__ hs, const float* __restrict__ ln1) {
    __shared__ float red[32];
    int bj = blockIdx.x;
    int b = bj >> 9;
    int row = g_idx[bj];
    const float4* src = (const float4*)(hs + ((size_t)(b*TT + row)) * DD);
    float4 x = src[threadIdx.x];
    float ss = x.x*x.x + x.y*x.y + x.z*x.z + x.w*x.w;
    float tot = blk_sum(ss, red);
    float r = rsqrtf(tot / (float)DD + 1e-6f);
    ((float4*)g_xsel)[bj*256 + threadIdx.x] = x;
    float4 w = ((const float4*)ln1)[threadIdx.x];
    uint32_t lo = pack_bf2(x.x*r*w.x, x.y*r*w.y);
    uint32_t hi = pack_bf2(x.z*r*w.z, x.w*r*w.w);
    *(uint2*)&g_hb[(size_t)bj*DD + threadIdx.x*4] = make_uint2(lo, hi);
}

// ---------------- combine wo split-K partials + rmsnorm2 -> bf16 -------------
__global__ void combine_rms2(const float* __restrict__ ln2) {
    __shared__ float red[32];
    int bj = blockIdx.x;
    int i = bj*256 + threadIdx.x;
    float4 xs = ((const float4*)g_xsel)[i];
    float4 p0 = ((const float4*)g_q)[i];
    float4 p1 = ((const float4*)g_k)[i];
    float4 x = make_float4(xs.x + p0.x + p1.x, xs.y + p0.y + p1.y,
                           xs.z + p0.z + p1.z, xs.w + p0.w + p1.w);
    ((float4*)g_x1)[i] = x;
    float ss = x.x*x.x + x.y*x.y + x.z*x.z + x.w*x.w;
    float tot = blk_sum(ss, red);
    float r = rsqrtf(tot / (float)DD + 1e-6f);
    float4 w = ((const float4*)ln2)[threadIdx.x];
    uint32_t lo = pack_bf2(x.x*r*w.x, x.y*r*w.y);
    uint32_t hi = pack_bf2(x.z*r*w.z, x.w*r*w.w);
    *(uint2*)&g_h2b[(size_t)bj*DD + threadIdx.x*4] = make_uint2(lo, hi);
}

// ---------------- BF16 tensor-core GEMM (2-stage cp.async, split-K) -----------
// out_mode: 0 = fp32, 1 = fp32 tf32-rounded, 5 = QKV (rope fused for z<2, rnd)
#define ASTR 20
#define BSTR 136
__global__ __launch_bounds__(256) void gemm_bf(
    const __nv_bfloat16* __restrict__ A,
    const uint32_t* __restrict__ B0, const uint32_t* __restrict__ B1, const uint32_t* __restrict__ B2,
    float* __restrict__ C0, float* __restrict__ C1, float* __restrict__ C2,
    int M, int N, int Ktot, int Klen, int koff_step, int out_mode)
{
    const uint32_t* B = (blockIdx.z == 0) ? B0 : (blockIdx.z == 1 ? B1 : B2);
    float*          C = (blockIdx.z == 0) ? C0 : (blockIdx.z == 1 ? C1 : C2);
    int kbase = (blockIdx.z * koff_step) >> 1;

    __shared__ uint32_t As[2][128][ASTR];
    __shared__ uint32_t Bs[2][16][BSTR];
    int tid = threadIdx.x;
    int w = tid >> 5, lane = tid & 31;
    int wm = w >> 1, wn = w & 1;
    int gid = lane >> 2, tid4 = lane & 3;
    int row0 = blockIdx.y * 128, col0 = blockIdx.x * 128;

    const uint32_t* Au = (const uint32_t*)A;
    int K2tot = Ktot >> 1;

    int arr = tid >> 1;
    int arc = (tid & 1) * 8;
    int brw = tid >> 4;
    int bcc = (tid & 15) * 4;

    float acc[2][8][4];
    #pragma unroll
    for (int i = 0; i < 2; i++)
        #pragma unroll
        for (int j = 0; j < 8; j++)
            #pragma unroll
            for (int c = 0; c < 4; c++) acc[i][j][c] = 0.f;

    int nt = Klen / 32;

    cp16(&As[0][arr][arc],     &Au[(size_t)(row0 + arr)*K2tot + kbase + arc]);
    cp16(&As[0][arr][arc + 4], &Au[(size_t)(row0 + arr)*K2tot + kbase + arc + 4]);
    cp16(&Bs[0][brw][bcc],      &B[(size_t)(kbase + brw)*N + col0 + bcc]);
    cp16(&Bs[0][brw][bcc + 64], &B[(size_t)(kbase + brw)*N + col0 + bcc + 64]);
    asm volatile("cp.async.commit_group;");

    int buf = 0;
    for (int t = 0; t < nt; t++) {
        if (t + 1 < nt) {
            int k2o = kbase + (t + 1) * 16;
            cp16(&As[buf^1][arr][arc],     &Au[(size_t)(row0 + arr)*K2tot + k2o + arc]);
            cp16(&As[buf^1][arr][arc + 4], &Au[(size_t)(row0 + arr)*K2tot + k2o + arc + 4]);
            cp16(&Bs[buf^1][brw][bcc],      &B[(size_t)(k2o + brw)*N + col0 + bcc]);
            cp16(&Bs[buf^1][brw][bcc + 64], &B[(size_t)(k2o + brw)*N + col0 + bcc + 64]);
            asm volatile("cp.async.commit_group;");
            asm volatile("cp.async.wait_group 1;");
        } else {
            asm volatile("cp.async.wait_group 0;");
        }
        __syncthreads();

        #pragma unroll
        for (int ks = 0; ks < 2; ks++) {
            int kb = ks * 8;
            uint32_t af[2][4];
            #pragma unroll
            for (int mt = 0; mt < 2; mt++) {
                int rm = wm*32 + mt*16;
                af[mt][0] = As[buf][rm + gid    ][kb + tid4    ];
                af[mt][1] = As[buf][rm + gid + 8][kb + tid4    ];
                af[mt][2] = As[buf][rm + gid    ][kb + tid4 + 4];
                af[mt][3] = As[buf][rm + gid + 8][kb + tid4 + 4];
            }
            #pragma unroll
            for (int n2 = 0; n2 < 8; n2++) {
                int cn = wn*64 + n2*8 + gid;
                uint32_t b0 = Bs[buf][kb + tid4    ][cn];
                uint32_t b1 = Bs[buf][kb + tid4 + 4][cn];
                MMA_BF16(acc[0][n2][0], acc[0][n2][1], acc[0][n2][2], acc[0][n2][3],
                         af[0][0], af[0][1], af[0][2], af[0][3], b0, b1);
                MMA_BF16(acc[1][n2][0], acc[1][n2][1], acc[1][n2][2], acc[1][n2][3],
                         af[1][0], af[1][1], af[1][2], af[1][3], b0, b1);
            }
        }
        __syncthreads();
        buf ^= 1;
    }

    if (out_mode == 5) {
        bool dorope = (blockIdx.z < 2);
        #pragma unroll
        for (int mt = 0; mt < 2; mt++) {
            int row = row0 + wm*32 + mt*16 + gid;
            float posA = 0.f, posB = 0.f;
            if (dorope) {
                posA = (float)g_idx[row];
                posB = (float)g_idx[row + 8];
            }
            #pragma unroll
            for (int n2 = 0; n2 < 4; n2++) {
                int col = col0 + wn*64 + n2*8 + tid4*2;
                float x1a = acc[mt][n2][0],   x1b = acc[mt][n2][1];
                float x1c = acc[mt][n2][2],   x1d = acc[mt][n2][3];
                float x2a = acc[mt][n2+4][0], x2b = acc[mt][n2+4][1];
                float x2c = acc[mt][n2+4][2], x2d = acc[mt][n2+4][3];
                float o1a, o1b, o1c, o1d, o2a, o2b, o2c, o2d;
                if (dorope) {
                    int d0 = col & 63;
                    float inv0 = expf(-logf(10000.f) * (float)d0 / 32.f);
                    float inv1 = expf(-logf(10000.f) * (float)(d0 + 1) / 32.f);
                    float cA0, sA0, cA1, sA1, cB0, sB0, cB1, sB1;
                    __sincosf(posA * inv0, &sA0, &cA0);
                    __sincosf(posA * inv1, &sA1, &cA1);
                    __sincosf(posB * inv0, &sB0, &cB0);
                    __sincosf(posB * inv1, &sB1, &cB1);
                    o1a = x1a*cA0 - x2a*sA0;  o2a = x2a*cA0 + x1a*sA0;
                    o1b = x1b*cA1 - x2b*sA1;  o2b = x2b*cA1 + x1b*sA1;
                    o1c = x1c*cB0 - x2c*sB0;  o2c = x2c*cB0 + x1c*sB0;
                    o1d = x1d*cB1 - x2d*sB1;  o2d = x2d*cB1 + x1d*sB1;
                } else {
                    o1a = x1a; o1b = x1b; o1c = x1c; o1d = x1d;
                    o2a = x2a; o2b = x2b; o2c = x2c; o2d = x2d;
                }
                *(float2*)&C[(size_t)row*N + col]          = make_float2(rnd(o1a), rnd(o1b));
                *(float2*)&C[(size_t)(row+8)*N + col]      = make_float2(rnd(o1c), rnd(o1d));
                *(float2*)&C[(size_t)row*N + col + 32]     = make_float2(rnd(o2a), rnd(o2b));
                *(float2*)&C[(size_t)(row+8)*N + col + 32] = make_float2(rnd(o2c), rnd(o2d));
            }
        }
    } else {
        #pragma unroll
        for (int mt = 0; mt < 2; mt++) {
            int row = row0 + wm*32 + mt*16 + gid;
            #pragma unroll
            for (int n2 = 0; n2 < 8; n2++) {
                int col = col0 + wn*64 + n2*8 + tid4*2;
                float2 v0 = make_float2(acc[mt][n2][0], acc[mt][n2][1]);
                float2 v1 = make_float2(acc[mt][n2][2], acc[mt][n2][3]);
                if (out_mode == 1) {
                    v0.x = rnd(v0.x); v0.y = rnd(v0.y);
                    v1.x = rnd(v1.x); v1.y = rnd(v1.y);
                }
                *(float2*)&C[(size_t)row*N + col]     = v0;
                *(float2*)&C[(size_t)(row+8)*N + col] = v1;
            }
        }
    }
}

// ---------------- tf32 flash attention, bf16 output, heavy-first --------------
__global__ __launch_bounds__(128) void attn_tc() {
    __shared__ float Qs[64][68];
    __shared__ float Ks[64][68];
    __shared__ float Vs[64][72];
    __shared__ float Ps[4][16][68];
    int qt = gridDim.x - 1 - blockIdx.x;
    int h = blockIdx.y, b = blockIdx.z;
    int tid = threadIdx.x, w = tid >> 5, lane = tid & 31;
    int gid = lane >> 2, tid4 = lane & 3;

    for (int f = tid; f < 64*16; f += 128) {
        int q = f >> 4, d4 = (f & 15) << 2;
        *(float4*)&Qs[q][d4] =
            *(const float4*)&g_q[((size_t)((b*KK + qt*64 + q)*HEADS + h))*HDIM + d4];
    }

    int r0g = qt*64 + w*16 + gid;
    int r1g = r0g + 8;

    float m0 = -1e30f, m1 = -1e30f, l0 = 0.f, l1 = 0.f;
    float oa[8][4];
    #pragma unroll
    for (int n2 = 0; n2 < 8; n2++)
        #pragma unroll
        for (int c = 0; c < 4; c++) oa[n2][c] = 0.f;

    for (int kt = 0; kt <= qt; kt++) {
        __syncthreads();
        for (int f = tid; f < 64*16; f += 128) {
            int k = f >> 4, d4 = (f & 15) << 2;
            size_t base = ((size_t)((b*KK + kt*64 + k)*HEADS + h))*HDIM + d4;
            *(float4*)&Ks[k][d4] = *(const float4*)&g_k[base];
            *(float4*)&Vs[k][d4] = *(const float4*)&g_v[base];
        }
        __syncthreads();

        float sc[8][4];
        #pragma unroll
        for (int n2 = 0; n2 < 8; n2++)
            #pragma unroll
            for (int c = 0; c < 4; c++) sc[n2][c] = 0.f;

        #pragma unroll
        for (int ks = 0; ks < 8; ks++) {
            int kb = ks * 8;
            uint32_t a0 = __float_as_uint(Qs[w*16 + gid    ][kb + tid4    ]);
            uint32_t a1 = __float_as_uint(Qs[w*16 + gid + 8][kb + tid4    ]);
            uint32_t a2 = __float_as_uint(Qs[w*16 + gid    ][kb + tid4 + 4]);
            uint32_t a3 = __float_as_uint(Qs[w*16 + gid + 8][kb + tid4 + 4]);
            #pragma unroll
            for (int n2 = 0; n2 < 8; n2++) {
                uint32_t b0 = __float_as_uint(Ks[n2*8 + gid][kb + tid4    ]);
                uint32_t b1 = __float_as_uint(Ks[n2*8 + gid][kb + tid4 + 4]);
                MMA_TF32(sc[n2][0], sc[n2][1], sc[n2][2], sc[n2][3],
                         a0, a1, a2, a3, b0, b1);
            }
        }

        bool diag = (kt == qt);
        float mx0 = -1e30f, mx1 = -1e30f;
        #pragma unroll
        for (int n2 = 0; n2 < 8; n2++) {
            int col = kt*64 + n2*8 + 2*tid4;
            sc[n2][0] *= 0.125f; sc[n2][1] *= 0.125f;
            sc[n2][2] *= 0.125f; sc[n2][3] *= 0.125f;
            if (diag) {
                if (col     > r0g) sc[n2][0] = -1e30f;
                if (col + 1 > r0g) sc[n2][1] = -1e30f;
                if (col     > r1g) sc[n2][2] = -1e30f;
                if (col + 1 > r1g) sc[n2][3] = -1e30f;
            }
            mx0 = fmaxf(mx0, fmaxf(sc[n2][0], sc[n2][1]));
            mx1 = fmaxf(mx1, fmaxf(sc[n2][2], sc[n2][3]));
        }
        #pragma unroll
        for (int o = 1; o <= 2; o <<= 1) {
            mx0 = fmaxf(mx0, __shfl_xor_sync(0xffffffffu, mx0, o));
            mx1 = fmaxf(mx1, __shfl_xor_sync(0xffffffffu, mx1, o));
        }
        float mn0 = fmaxf(m0, mx0), mn1 = fmaxf(m1, mx1);
        float cor0 = __expf(m0 - mn0), cor1 = __expf(m1 - mn1);
        m0 = mn0; m1 = mn1;
        float rs0 = 0.f, rs1 = 0.f;
        #pragma unroll
        for (int n2 = 0; n2 < 8; n2++) {
            float p0 = __expf(sc[n2][0] - mn0);
            float p1 = __expf(sc[n2][1] - mn0);
            float p2 = __expf(sc[n2][2] - mn1);
            float p3 = __expf(sc[n2][3] - mn1);
            rs0 += p0 + p1; rs1 += p2 + p3;
            *(float2*)&Ps[w][gid    ][n2*8 + 2*tid4] = make_float2(rnd(p0), rnd(p1));
            *(float2*)&Ps[w][gid + 8][n2*8 + 2*tid4] = make_float2(rnd(p2), rnd(p3));
        }
        #pragma unroll
        for (int o = 1; o <= 2; o <<= 1) {
            rs0 += __shfl_xor_sync(0xffffffffu, rs0, o);
            rs1 += __shfl_xor_sync(0xffffffffu, rs1, o);
        }
        l0 = l0 * cor0 + rs0;
        l1 = l1 * cor1 + rs1;
        #pragma unroll
        for (int n2 = 0; n2 < 8; n2++) {
            oa[n2][0] *= cor0; oa[n2][1] *= cor0;
            oa[n2][2] *= cor1; oa[n2][3] *= cor1;
        }
        __syncwarp();

        #pragma unroll
        for (int ks = 0; ks < 8; ks++) {
            uint32_t a0 = __float_as_uint(Ps[w][gid    ][ks*8 + tid4    ]);
            uint32_t a1 = __float_as_uint(Ps[w][gid + 8][ks*8 + tid4    ]);
            uint32_t a2 = __float_as_uint(Ps[w][gid    ][ks*8 + tid4 + 4]);
            uint32_t a3 = __float_as_uint(Ps[w][gid + 8][ks*8 + tid4 + 4]);
            #pragma unroll
            for (int n2 = 0; n2 < 8; n2++) {
                uint32_t b0 = __float_as_uint(Vs[ks*8 + tid4    ][n2*8 + gid]);
                uint32_t b1 = __float_as_uint(Vs[ks*8 + tid4 + 4][n2*8 + gid]);
                MMA_TF32(oa[n2][0], oa[n2][1], oa[n2][2], oa[n2][3],
                         a0, a1, a2, a3, b0, b1);
            }
        }
        __syncwarp();
    }

    float i0 = 1.f / l0, i1 = 1.f / l1;
    #pragma unroll
    for (int n2 = 0; n2 < 8; n2++) {
        int d = n2*8 + 2*tid4;
        uint32_t p0 = pack_bf2(oa[n2][0]*i0, oa[n2][1]*i0);
        uint32_t p1 = pack_bf2(oa[n2][2]*i1, oa[n2][3]*i1);
        *(uint32_t*)&g_ob[((size_t)((b*KK + r0g)*HEADS + h))*HDIM + d] = p0;
        *(uint32_t*)&g_ob[((size_t)((b*KK + r1g)*HEADS + h))*HDIM + d] = p1;
    }
}

// ---------------- silu(gate)*up -> bf16 --------------------------------------
__global__ void silu_mul_kernel() {
    int i = blockIdx.x * blockDim.x + threadIdx.x;
    const int N4 = BKr*FF/4;
    if (i >= N4) return;
    float4 g = ((const float4*)g_gateb)[i];
    float4 u = ((const float4*)g_upb)[i];
    float a = g.x / (1.f + __expf(-g.x)) * u.x;
    float b = g.y / (1.f + __expf(-g.y)) * u.y;
    float c = g.z / (1.f + __expf(-g.z)) * u.z;
    float d = g.w / (1.f + __expf(-g.w)) * u.w;
    *(uint2*)&g_mlpa[(size_t)i*4] = make_uint2(pack_bf2(a, b), pack_bf2(c, d));
}

// ---------------- scatter: combine down split-K + gated residual --------------
__global__ void scatter_kernel(float* __restrict__ out) {
    int bj = blockIdx.x;
    int b = bj >> 9;
    int row = g_idx[bj];
    float gate = g_gates[bj];
    int i = bj*256 + threadIdx.x;
    float4 xs = ((const float4*)g_xsel)[i];
    float4 x1 = ((const float4*)g_x1)[i];
    float4 p0 = ((const float4*)g_q)[i];
    float4 p1 = ((const float4*)g_k)[i];
    float4 o;
    o.x = xs.x + gate*((x1.x + p0.x + p1.x) - xs.x);
    o.y = xs.y + gate*((x1.y + p0.y + p1.y) - xs.y);
    o.z = xs.z + gate*((x1.z + p0.z + p1.z) - xs.z);
    o.w = xs.w + gate*((x1.w + p0.w + p1.w) - xs.w);
    ((float4*)out)[((size_t)(b*TT + row))*256 + threadIdx.x] = o;
}

// ---------------- launch -------------------------------------------------------
extern "C" void kernel_launch(void* const* d_in, const int* in_sizes, int n_in,
                              void* d_out, int out_size) {
    const float* hs  = (const float*)d_in[0];
    const float* wr  = (const float*)d_in[1];
    const float* wq  = (const float*)d_in[2];
    const float* wk  = (const float*)d_in[3];
    const float* wv  = (const float*)d_in[4];
    const float* wo  = (const float*)d_in[5];
    const float* ln1 = (const float*)d_in[6];
    const float* ln2 = (const float*)d_in[7];
    const float* wg  = (const float*)d_in[8];
    const float* wu  = (const float*)d_in[9];
    const float* wd  = (const float*)d_in[10];
    float* out = (float*)d_out;

    static cudaStream_t s2 = nullptr;
    static cudaEvent_t evA = nullptr, evB = nullptr;
    if (!s2) {
        cudaStreamCreateWithFlags(&s2, cudaStreamNonBlocking);
        cudaEventCreateWithFlags(&evA, cudaEventDisableTiming);
        cudaEventCreateWithFlags(&evB, cudaEventDisableTiming);
    }

    float *p_q, *p_k, *p_v, *p_gate, *p_up;
    __nv_bfloat16 *p_hb, *p_ob, *p_h2b, *p_mlpa;
    uint32_t *p_wp;
    cudaGetSymbolAddress((void**)&p_q,    g_q);
    cudaGetSymbolAddress((void**)&p_k,    g_k);
    cudaGetSymbolAddress((void**)&p_v,    g_v);
    cudaGetSymbolAddress((void**)&p_gate, g_gateb);
    cudaGetSymbolAddress((void**)&p_up,   g_upb);
    cudaGetSymbolAddress((void**)&p_hb,   g_hb);
    cudaGetSymbolAddress((void**)&p_ob,   g_ob);
    cudaGetSymbolAddress((void**)&p_h2b,  g_h2b);
    cudaGetSymbolAddress((void**)&p_mlpa, g_mlpa);
    cudaGetSymbolAddress((void**)&p_wp,   g_wpack);

    uint32_t* rwq = p_wp;
    uint32_t* rwk = p_wp + NW1/2;
    uint32_t* rwv = p_wp + 2*(NW1/2);
    uint32_t* rwo = p_wp + 3*(NW1/2);
    uint32_t* rwg = p_wp + 4*(NW1/2);
    uint32_t* rwu = p_wp + 4*(NW1/2) + NWF/2;
    uint32_t* rwd = p_wp + 4*(NW1/2) + 2*(NWF/2);

    // round-14 schedule (best measured): side stream = copy then pack,
    // single join before QKV.
    cudaEventRecord(evA, 0);
    cudaStreamWaitEvent(s2, evA, 0);
    cudaMemcpyAsync(out, hs, (size_t)BT*DD*sizeof(float), cudaMemcpyDeviceToDevice, s2);
    pack_all<<<2048, 256, 0, s2>>>(wq, wk, wv, wo, wg, wu, wd);
    cudaEventRecord(evB, s2);

    router_kernel<<<BT/8, 256>>>(hs, wr);
    aux1_kernel<<<64, 256>>>();
    topk_kernel<<<BB, 1024>>>();
    gather_rms1<<<BKr, 256>>>(hs, ln1);

    cudaStreamWaitEvent(0, evB, 0);

    // fused QKV with in-epilogue RoPE (q,k) + tf32 rounding
    gemm_bf<<<dim3(DD/128, BKr/128, 3), 256>>>(p_hb, rwq, rwk, rwv,
                                               p_q, p_k, p_v,
                                               BKr, DD, DD, DD, 0, 5);

    // aux2 off the critical path: overlaps with QKV tail
    aux2_kernel<<<1, 1024>>>(out, out_size - 1);

    attn_tc<<<dim3(KK/64, HEADS, BB), 128>>>();

    // wo: split-K x2 into g_q/g_k partials
    gemm_bf<<<dim3(DD/128, BKr/128, 2), 256>>>(p_ob, rwo, rwo, rwo,
                                               p_q, p_k, p_k,
                                               BKr, DD, DD, DD/2, DD/2, 0);
    combine_rms2<<<BKr, 256>>>(ln2);

    // gate/up fused
    gemm_bf<<<dim3(FF/128, BKr/128, 2), 256>>>(p_h2b, rwg, rwu, rwu,
                                               p_gate, p_up, p_up,
                                               BKr, FF, DD, DD, 0, 0);
    silu_mul_kernel<<<(BKr*FF/4 + 255)/256, 256>>>();

    // down: split-K x2 into g_q/g_k partials
    gemm_bf<<<dim3(DD/128, BKr/128, 2), 256>>>(p_mlpa, rwd, rwd, rwd,
                                               p_q, p_k, p_k,
                                               BKr, DD, FF, FF/2, FF/2, 0);

    scatter_kernel<<<BKr, 256>>>(out);
}